// round 12
// baseline (speedup 1.0000x reference)
#include <cuda_runtime.h>
#include <cuda_bf16.h>
#include <math.h>
#include <stdint.h>
#include <mma.h>

using namespace nvcuda;

#define NN 10000
#define NE 200000
#define FD 128
#define NBD 20
#define NF (NN*FD)
#define N3F (NN*3*FD)
#define LDB 136          // bf16 tile leading dim
#define SCRLD 20         // fp32 scratch leading dim
#define TROWS 64         // rows per CTA tile

// byte offsets inside dynamic SMEM (per 128-thread CTA)
#define OFF_AH   0                 // 64 x 136 bf16 = 17408
#define OFF_AL   17408
#define OFF_WB   34816             // 2 weight-slice buffers x 8704 B (also holds EW 16384 in EPI4 prologue)
#define OFF_SCR  52224             // 4 warps x 16*20*4 = 5120
#define OFF_B1   57344
#define OFF_B2   57856
#define SMEM_TOT 58368
#define OFF_EB   58368             // EPI4: empb 512
#define SMEM_T4  58880

#define WSLICE_BF 4352             // bf16 per k-slice block (H 16x136 + L 16x136)
#define WMAT_BF  (8*WSLICE_BF)     // bf16 per prepared matrix

// ---------------- scratch (device globals; no allocation) ----------------
__device__ float g_H[NF];
__device__ float g_MSG[NE*FD];
__device__ float g_AGG1[N3F];
__device__ float g_ATOM[NF];
__device__ float g_EQ3[NF];
__device__ float g_U[NF];
__device__ __nv_bfloat16 g_WP[10*WMAT_BF];   // pre-split weights (hi/lo k-slices)
__device__ __nv_bfloat16 g_WPE[2*32*128];    // pre-split empW: hi [32][128], lo [32][128]

// ---------------- helpers ----------------
__device__ __forceinline__ float4 ld4(const float* p){ return *reinterpret_cast<const float4*>(p); }
__device__ __forceinline__ void st4(float* p, float4 v){ *reinterpret_cast<float4*>(p) = v; }
__device__ __forceinline__ float silu_f(float x){ return x * (1.0f/(1.0f + __expf(-x))); }
__device__ __forceinline__ void red4(float* p, float4 v){
    asm volatile("red.global.add.v4.f32 [%0], {%1,%2,%3,%4};"
        :: "l"(p), "f"(v.x), "f"(v.y), "f"(v.z), "f"(v.w) : "memory");
}
__device__ __forceinline__ uint32_t packbf2(float a, float b){
    __nv_bfloat162 t = __floats2bfloat162_rn(a, b);
    return *reinterpret_cast<uint32_t*>(&t);
}
__device__ __forceinline__ float bf2f(uint32_t u, int half){
    __nv_bfloat162 t = *reinterpret_cast<__nv_bfloat162*>(&u);
    return half ? __bfloat162float(__high2bfloat16(t)) : __bfloat162float(__low2bfloat16(t));
}
__device__ __forceinline__ void cpasync16(uint32_t saddr, const void* gaddr){
    asm volatile("cp.async.cg.shared.global [%0], [%1], 16;" :: "r"(saddr), "l"(gaddr) : "memory");
}
__device__ __forceinline__ void cpcommit(){
    asm volatile("cp.async.commit_group;" ::: "memory");
}
template<int N> __device__ __forceinline__ void cpwait(){
    asm volatile("cp.async.wait_group %0;" :: "n"(N) : "memory");
}

// split x into hi(bf16) + lo(bf16 of residual); write 4 cols (8B) to each tile
__device__ __forceinline__ void split_store4(char* sb, int offH, int offL,
                                             int row, int col, float4 v){
    uint32_t h0 = packbf2(v.x, v.y);
    uint32_t h1 = packbf2(v.z, v.w);
    float4 r;
    r.x = v.x - bf2f(h0,0); r.y = v.y - bf2f(h0,1);
    r.z = v.z - bf2f(h1,0); r.w = v.w - bf2f(h1,1);
    uint32_t l0 = packbf2(r.x, r.y);
    uint32_t l1 = packbf2(r.z, r.w);
    uint2 hh; hh.x = h0; hh.y = h1;
    uint2 ll; ll.x = l0; ll.y = l1;
    *reinterpret_cast<uint2*>(sb + offH + (row*LDB + col)*2) = hh;
    *reinterpret_cast<uint2*>(sb + offL + (row*LDB + col)*2) = ll;
}

// ---------------- weight prep: fp32 [k][c] -> bf16 hi/lo k-slice blocks ----------------
struct WPtrs { const float* w[11]; };

__global__ void prep_w(WPtrs P){
    if (blockIdx.x < 80){
        int m  = blockIdx.x >> 3;
        int ks = blockIdx.x & 7;
        const float* W = P.w[m];
        __nv_bfloat16* dst = g_WP + m*WMAT_BF + ks*WSLICE_BF;
        for (int e = threadIdx.x; e < 16*FD; e += blockDim.x){
            int kr = e >> 7, c = e & 127;
            float w = W[(ks*16 + kr)*FD + c];
            __nv_bfloat16 h = __float2bfloat16_rn(w);
            __nv_bfloat16 l = __float2bfloat16_rn(w - __bfloat162float(h));
            dst[kr*LDB + c]        = h;
            dst[2176 + kr*LDB + c] = l;
        }
    } else {
        // empW [20][128] -> g_WPE hi/lo [32][128] with zero padding rows 20..31
        const float* W = P.w[10];
        for (int e = threadIdx.x; e < 32*128; e += blockDim.x){
            int k = e >> 7, c = e & 127;
            float w = (k < NBD) ? W[k*FD + c] : 0.f;
            __nv_bfloat16 h = __float2bfloat16_rn(w);
            __nv_bfloat16 l = __float2bfloat16_rn(w - __bfloat162float(h));
            g_WPE[k*128 + c]        = h;
            g_WPE[4096 + k*128 + c] = l;
        }
    }
}

// ---------------- init ----------------
__global__ void init_kernel(const float* __restrict__ atom, const float* __restrict__ force,
                            const float* __restrict__ disp, float* __restrict__ out){
    int i = blockIdx.x*blockDim.x + threadIdx.x;
    if (i < N3F/4) {
        ((float4*)(out + NF))[i]        = ((const float4*)force)[i];
        ((float4*)(out + NF + N3F))[i]  = ((const float4*)disp)[i];
        ((float4*)g_AGG1)[i]            = make_float4(0.f,0.f,0.f,0.f);
    }
    if (i < NF/4) ((float4*)g_ATOM)[i] = ((const float4*)atom)[i];
}

// ---------------- bf16x3 wmma fused 2-layer MLP, weight-streaming ----------------
// 128 threads, 64-row tiles, warp block 32x64, 3 CTAs/SM.
// EPI 0: Y with biases   EPI 3: Y no-bias
// EPI 2: red(accout[src,d,:], m * disp_node[dst,d,:])
// EPI 4: eq1 with fused edge message: prologue computes E = dist@empW (tensor
//        cores, bf16x3), msg = (E+b)*h[src]*h[dst]; writes msg to Y (=g_MSG),
//        red4s msg into g_ATOM, splits msg into the A tiles; main pipeline then
//        runs the eq1 MLP and scatters into accout. `dispn` slot carries dist.
template<int EPI>
__global__ void __launch_bounds__(128,3)
mlp2_ws(const float* __restrict__ X, int nrows,
        const __nv_bfloat16* __restrict__ w1, const __nv_bfloat16* __restrict__ w2,
        const float* __restrict__ b1, const float* __restrict__ b2,
        float* __restrict__ Y,
        const int* __restrict__ eidx, const float* __restrict__ dispe,
        const float* __restrict__ dispn, float* __restrict__ accout,
        const float* __restrict__ empb)
{
    extern __shared__ char sb[];
    float* sB1 = (float*)(sb + OFF_B1);
    float* sB2 = (float*)(sb + OFF_B2);

    const int tid  = threadIdx.x;
    const int wid  = tid >> 5;       // 4 warps
    const int lane = tid & 31;

    sB1[tid] = b1 ? b1[tid] : 0.f;
    sB2[tid] = b2 ? b2[tid] : 0.f;
    if (EPI == 4){
        float* sEB = (float*)(sb + OFF_EB);
        sEB[tid] = empb[tid];
    }
    __syncthreads();

    const __nv_bfloat16* pAH = (const __nv_bfloat16*)(sb + OFF_AH);
    const __nv_bfloat16* pAL = (const __nv_bfloat16*)(sb + OFF_AL);
    float* scr = (float*)(sb + OFF_SCR) + wid*16*SCRLD;
    const uint32_t wb0 = (uint32_t)__cvta_generic_to_shared(sb + OFF_WB);

    const int ntiles = (nrows + TROWS - 1) / TROWS;
    const int pr = wid >> 1;            // pair (row group) 0..1
    const int sub = wid & 1;            // column half
    const int wr = pr * 32;
    const int wc = sub * 64;
    const int lr = lane >> 1;           // 0..15
    const int lc = (lane & 1) * 8;      // 0 or 8

    auto copy_slice = [&](int buf, const __nv_bfloat16* src){
        uint32_t dst = wb0 + buf*8704;
        const char* s = (const char*)src;
        #pragma unroll
        for (int j = 0; j < 5; j++){
            int idx = tid + j*128;
            if (idx < 544) cpasync16(dst + idx*16, s + idx*16);
        }
    };

    for (int tile = blockIdx.x; tile < ntiles; tile += gridDim.x){
        const int row0 = tile * TROWS;

        if (EPI == 4){
            // ---- EW tiles (bf16 hi/lo, 16KB) into the WB region ----
            {
                const char* s = (const char*)g_WPE;
                #pragma unroll
                for (int j = 0; j < 8; j++){
                    int idx = tid + j*128;
                    cpasync16(wb0 + idx*16, s + idx*16);
                }
                cpcommit();
            }
            // ---- dist tile (64 x 32, cols 20..31 zero) split hi/lo into A tiles ----
            #pragma unroll 4
            for (int rr = 0; rr < 16; rr++){
                int rl = wid*16 + rr;
                int e  = row0 + rl;
                float d = (lane < NBD && e < nrows) ? __ldg(dispn + (size_t)e*NBD + lane) : 0.f;
                __nv_bfloat16 h = __float2bfloat16_rn(d);
                __nv_bfloat16 l = __float2bfloat16_rn(d - __bfloat162float(h));
                ((__nv_bfloat16*)(sb + OFF_AH))[rl*LDB + lane] = h;
                ((__nv_bfloat16*)(sb + OFF_AL))[rl*LDB + lane] = l;
            }
            cpwait<0>();
            __syncthreads();

            // ---- E = distTile @ EW (bf16x3, 2 k-steps) ----
            wmma::fragment<wmma::accumulator,16,16,16,float> eacc[2][4];
            #pragma unroll
            for (int p = 0; p < 2; p++)
                #pragma unroll
                for (int ct = 0; ct < 4; ct++) wmma::fill_fragment(eacc[p][ct], 0.f);
            #pragma unroll
            for (int ks = 0; ks < 2; ks++){
                const __nv_bfloat16* bufH = (const __nv_bfloat16*)(sb + OFF_WB);
                const __nv_bfloat16* bufL = bufH + 4096;
                wmma::fragment<wmma::matrix_a,16,16,16,__nv_bfloat16,wmma::row_major> aH[2], aL[2];
                #pragma unroll
                for (int p = 0; p < 2; p++){
                    wmma::load_matrix_sync(aH[p], pAH + (wr + p*16)*LDB + ks*16, LDB);
                    wmma::load_matrix_sync(aL[p], pAL + (wr + p*16)*LDB + ks*16, LDB);
                }
                #pragma unroll
                for (int ct = 0; ct < 4; ct++){
                    wmma::fragment<wmma::matrix_b,16,16,16,__nv_bfloat16,wmma::row_major> bH, bL;
                    wmma::load_matrix_sync(bH, bufH + ks*16*128 + wc + ct*16, 128);
                    wmma::load_matrix_sync(bL, bufL + ks*16*128 + wc + ct*16, 128);
                    #pragma unroll
                    for (int p = 0; p < 2; p++){
                        wmma::mma_sync(eacc[p][ct], aH[p], bL, eacc[p][ct]);
                        wmma::mma_sync(eacc[p][ct], aL[p], bH, eacc[p][ct]);
                        wmma::mma_sync(eacc[p][ct], aH[p], bH, eacc[p][ct]);
                    }
                }
            }
            __syncthreads();   // all E reads of A(dist) + EW(WB) done before overwrite

            // ---- msg = (E + eb) * h[src] * h[dst]; store/scatter/split ----
            const float* sEB = (const float*)(sb + OFF_EB);
            #pragma unroll
            for (int p = 0; p < 2; p++){
                const int row = row0 + wr + p*16 + lr;
                const bool valid = (row < nrows);
                int s = 0, t = 0;
                if (valid){
                    s = __ldg(eidx + row);
                    t = __ldg(eidx + NE + row);
                }
                #pragma unroll
                for (int ct = 0; ct < 4; ct++){
                    wmma::store_matrix_sync(scr, eacc[p][ct], SCRLD, wmma::mem_row_major);
                    __syncwarp();
                    int c0 = wc + ct*16 + lc;
                    float4 m0 = make_float4(0.f,0.f,0.f,0.f);
                    float4 m1 = make_float4(0.f,0.f,0.f,0.f);
                    if (valid){
                        float4 e0 = ld4(scr + lr*SCRLD + lc);
                        float4 e1 = ld4(scr + lr*SCRLD + lc + 4);
                        float4 eb0 = ld4(sEB + c0);
                        float4 eb1 = ld4(sEB + c0 + 4);
                        float4 hs0 = ld4(g_H + (size_t)s*FD + c0);
                        float4 hs1 = ld4(g_H + (size_t)s*FD + c0 + 4);
                        float4 ht0 = ld4(g_H + (size_t)t*FD + c0);
                        float4 ht1 = ld4(g_H + (size_t)t*FD + c0 + 4);
                        m0.x = (e0.x+eb0.x)*hs0.x*ht0.x; m0.y = (e0.y+eb0.y)*hs0.y*ht0.y;
                        m0.z = (e0.z+eb0.z)*hs0.z*ht0.z; m0.w = (e0.w+eb0.w)*hs0.w*ht0.w;
                        m1.x = (e1.x+eb1.x)*hs1.x*ht1.x; m1.y = (e1.y+eb1.y)*hs1.y*ht1.y;
                        m1.z = (e1.z+eb1.z)*hs1.z*ht1.z; m1.w = (e1.w+eb1.w)*hs1.w*ht1.w;
                        st4(Y + (size_t)row*FD + c0,     m0);
                        st4(Y + (size_t)row*FD + c0 + 4, m1);
                        red4(g_ATOM + (size_t)s*FD + c0,     m0);
                        red4(g_ATOM + (size_t)s*FD + c0 + 4, m1);
                    }
                    split_store4(sb, OFF_AH, OFF_AL, wr + p*16 + lr, c0,     m0);
                    split_store4(sb, OFF_AH, OFF_AL, wr + p*16 + lr, c0 + 4, m1);
                    __syncwarp();
                }
            }
            __syncthreads();   // msg tiles complete before stage-1 fragment reads
        } else {
            #pragma unroll 4
            for (int rr = 0; rr < 16; rr++){
                int rl  = wid*16 + rr;
                int row = row0 + rl;
                float4 v = make_float4(0.f,0.f,0.f,0.f);
                if (row < nrows) v = ld4(X + (size_t)row*FD + lane*4);
                split_store4(sb, OFF_AH, OFF_AL, rl, lane*4, v);
            }
        }

        copy_slice(0, w1); cpcommit();

        wmma::fragment<wmma::accumulator,16,16,16,float> acc[2][4];
        #pragma unroll
        for (int p = 0; p < 2; p++)
            #pragma unroll
            for (int ct = 0; ct < 4; ct++) wmma::fill_fragment(acc[p][ct], 0.f);

        // ================= stage 1: D = X @ W1 (bf16x3) =================
        #pragma unroll
        for (int ks = 0; ks < 8; ks++){
            if (ks < 7) copy_slice((ks+1)&1, w1 + (ks+1)*WSLICE_BF);
            else        copy_slice(0,        w2);
            cpcommit();
            cpwait<1>();
            __syncthreads();
            {
                const __nv_bfloat16* bufH = (const __nv_bfloat16*)(sb + OFF_WB + (ks&1)*8704);
                const __nv_bfloat16* bufL = bufH + 2176;
                wmma::fragment<wmma::matrix_a,16,16,16,__nv_bfloat16,wmma::row_major> aH[2], aL[2];
                #pragma unroll
                for (int p = 0; p < 2; p++){
                    wmma::load_matrix_sync(aH[p], pAH + (wr + p*16)*LDB + ks*16, LDB);
                    wmma::load_matrix_sync(aL[p], pAL + (wr + p*16)*LDB + ks*16, LDB);
                }
                #pragma unroll
                for (int ct = 0; ct < 4; ct++){
                    wmma::fragment<wmma::matrix_b,16,16,16,__nv_bfloat16,wmma::row_major> bH, bL;
                    wmma::load_matrix_sync(bH, bufH + wc + ct*16, LDB);
                    wmma::load_matrix_sync(bL, bufL + wc + ct*16, LDB);
                    #pragma unroll
                    for (int p = 0; p < 2; p++){
                        wmma::mma_sync(acc[p][ct], aH[p], bL, acc[p][ct]);
                        wmma::mma_sync(acc[p][ct], aL[p], bH, acc[p][ct]);
                        wmma::mma_sync(acc[p][ct], aH[p], bH, acc[p][ct]);
                    }
                }
            }
            __syncthreads();
        }

        // ---- silu(d + b1), re-split into A tiles ----
        #pragma unroll
        for (int p = 0; p < 2; p++){
            #pragma unroll
            for (int ct = 0; ct < 4; ct++){
                wmma::store_matrix_sync(scr, acc[p][ct], SCRLD, wmma::mem_row_major);
                __syncwarp();
                int c0 = wc + ct*16 + lc;
                float4 v0 = ld4(scr + lr*SCRLD + lc);
                float4 v1 = ld4(scr + lr*SCRLD + lc + 4);
                float4 bb0 = ld4(sB1 + c0);
                float4 bb1 = ld4(sB1 + c0 + 4);
                v0.x = silu_f(v0.x + bb0.x); v0.y = silu_f(v0.y + bb0.y);
                v0.z = silu_f(v0.z + bb0.z); v0.w = silu_f(v0.w + bb0.w);
                v1.x = silu_f(v1.x + bb1.x); v1.y = silu_f(v1.y + bb1.y);
                v1.z = silu_f(v1.z + bb1.z); v1.w = silu_f(v1.w + bb1.w);
                split_store4(sb, OFF_AH, OFF_AL, wr + p*16 + lr, c0,     v0);
                split_store4(sb, OFF_AH, OFF_AL, wr + p*16 + lr, c0 + 4, v1);
                __syncwarp();
            }
        }

        #pragma unroll
        for (int p = 0; p < 2; p++)
            #pragma unroll
            for (int ct = 0; ct < 4; ct++) wmma::fill_fragment(acc[p][ct], 0.f);

        // ================= stage 2: D = H @ W2 (bf16x3) =================
        #pragma unroll
        for (int ks = 0; ks < 8; ks++){
            if (ks < 7){ copy_slice((ks+1)&1, w2 + (ks+1)*WSLICE_BF); cpcommit(); cpwait<1>(); }
            else       { cpwait<0>(); }
            __syncthreads();
            {
                const __nv_bfloat16* bufH = (const __nv_bfloat16*)(sb + OFF_WB + (ks&1)*8704);
                const __nv_bfloat16* bufL = bufH + 2176;
                wmma::fragment<wmma::matrix_a,16,16,16,__nv_bfloat16,wmma::row_major> aH[2], aL[2];
                #pragma unroll
                for (int p = 0; p < 2; p++){
                    wmma::load_matrix_sync(aH[p], pAH + (wr + p*16)*LDB + ks*16, LDB);
                    wmma::load_matrix_sync(aL[p], pAL + (wr + p*16)*LDB + ks*16, LDB);
                }
                #pragma unroll
                for (int ct = 0; ct < 4; ct++){
                    wmma::fragment<wmma::matrix_b,16,16,16,__nv_bfloat16,wmma::row_major> bH, bL;
                    wmma::load_matrix_sync(bH, bufH + wc + ct*16, LDB);
                    wmma::load_matrix_sync(bL, bufL + wc + ct*16, LDB);
                    #pragma unroll
                    for (int p = 0; p < 2; p++){
                        wmma::mma_sync(acc[p][ct], aH[p], bL, acc[p][ct]);
                        wmma::mma_sync(acc[p][ct], aL[p], bH, acc[p][ct]);
                        wmma::mma_sync(acc[p][ct], aH[p], bH, acc[p][ct]);
                    }
                }
            }
            __syncthreads();
        }

        // ================= epilogue =================
        #pragma unroll
        for (int p = 0; p < 2; p++){
            const int row = row0 + wr + p*16 + lr;
            const bool valid = (row < nrows);
            int s = 0, t = 0;
            float d0 = 0.f, d1 = 0.f, d2 = 0.f;
            if (EPI == 4 && valid){
                s = __ldg(eidx + row);
                d0 = __ldg(dispe + (size_t)row*3 + 0);
                d1 = __ldg(dispe + (size_t)row*3 + 1);
                d2 = __ldg(dispe + (size_t)row*3 + 2);
            }
            if (EPI == 2 && valid){
                s = __ldg(eidx + row);
                t = __ldg(eidx + NE + row);
            }
            #pragma unroll
            for (int ct = 0; ct < 4; ct++){
                wmma::store_matrix_sync(scr, acc[p][ct], SCRLD, wmma::mem_row_major);
                __syncwarp();
                if (valid){
                    int c0 = wc + ct*16 + lc;
                    float4 m0 = ld4(scr + lr*SCRLD + lc);
                    float4 m1 = ld4(scr + lr*SCRLD + lc + 4);
                    float4 bb0 = ld4(sB2 + c0);
                    float4 bb1 = ld4(sB2 + c0 + 4);
                    m0.x += bb0.x; m0.y += bb0.y; m0.z += bb0.z; m0.w += bb0.w;
                    m1.x += bb1.x; m1.y += bb1.y; m1.z += bb1.z; m1.w += bb1.w;

                    if (EPI == 0 || EPI == 3){
                        st4(Y + (size_t)row*FD + c0,     m0);
                        st4(Y + (size_t)row*FD + c0 + 4, m1);
                    } else if (EPI == 4){
                        float* bp = accout + (size_t)s*3*FD + c0;
                        red4(bp,            make_float4(m0.x*d0, m0.y*d0, m0.z*d0, m0.w*d0));
                        red4(bp + 4,        make_float4(m1.x*d0, m1.y*d0, m1.z*d0, m1.w*d0));
                        red4(bp + FD,       make_float4(m0.x*d1, m0.y*d1, m0.z*d1, m0.w*d1));
                        red4(bp + FD + 4,   make_float4(m1.x*d1, m1.y*d1, m1.z*d1, m1.w*d1));
                        red4(bp + 2*FD,     make_float4(m0.x*d2, m0.y*d2, m0.z*d2, m0.w*d2));
                        red4(bp + 2*FD + 4, make_float4(m1.x*d2, m1.y*d2, m1.z*d2, m1.w*d2));
                    } else { // EPI == 2
                        const float* gp = dispn + (size_t)t*3*FD + c0;
                        float* bp = accout + (size_t)s*3*FD + c0;
                        #pragma unroll
                        for (int d = 0; d < 3; d++){
                            float4 g0 = ld4(gp + d*FD);
                            float4 g1 = ld4(gp + d*FD + 4);
                            red4(bp + d*FD,     make_float4(m0.x*g0.x, m0.y*g0.y, m0.z*g0.z, m0.w*g0.w));
                            red4(bp + d*FD + 4, make_float4(m1.x*g1.x, m1.y*g1.y, m1.z*g1.z, m1.w*g1.w));
                        }
                    }
                }
                __syncwarp();
            }
        }
        __syncthreads();
    }
}

// ---------------- force_out += agg1 ----------------
__global__ void force_add_kernel(float* __restrict__ outF){
    int i = blockIdx.x*blockDim.x + threadIdx.x;
    if (i < N3F/4){
        float4 a = ((float4*)g_AGG1)[i];
        float4 f = ((float4*)outF)[i];
        ((float4*)outF)[i] = make_float4(f.x+a.x, f.y+a.y, f.z+a.z, f.w+a.w);
    }
}

// ---------------- eq3: disp[src] += eq3_inv[dst] * agg1[dst] ----------------
__global__ void eq3_edge_kernel(const int* __restrict__ eidx, float* __restrict__ out_disp){
    const int tid  = threadIdx.x;
    const int lane = tid & 31;
    const int warp = (blockIdx.x*blockDim.x + tid) >> 5;
    const int nw   = (gridDim.x*blockDim.x) >> 5;
    for (int e = warp; e < NE; e += nw) {
        int s = __ldg(eidx + e);
        int t = __ldg(eidx + NE + e);
        float4 g = ld4(g_EQ3 + (size_t)t*FD + lane*4);
        #pragma unroll
        for (int d = 0; d < 3; d++) {
            float4 a = ld4(g_AGG1 + ((size_t)t*3 + d)*FD + lane*4);
            red4(out_disp + ((size_t)s*3 + d)*FD + lane*4,
                 make_float4(g.x*a.x, g.y*a.y, g.z*a.z, g.w*a.w));
        }
    }
}

// ---------------- final: inv_update + layernorm ----------------
__global__ void final_kernel(const float* __restrict__ outF, const float* __restrict__ outD,
                             const float* __restrict__ lng, const float* __restrict__ lnb,
                             float* __restrict__ outA){
    const int i = blockIdx.x;
    const int j = threadIdx.x;   // 128
    float c = 0.f;
    #pragma unroll
    for (int d = 0; d < 3; d++)
        c -= outF[((size_t)i*3 + d)*FD + j] * outD[((size_t)i*3 + d)*FD + j];
    float t = g_ATOM[(size_t)i*FD + j] + g_U[(size_t)i*FD + j] * c;

    __shared__ float red[4];
    float s = t;
    #pragma unroll
    for (int o = 16; o; o >>= 1) s += __shfl_xor_sync(0xffffffffu, s, o);
    if ((j & 31) == 0) red[j >> 5] = s;
    __syncthreads();
    float mu = (red[0]+red[1]+red[2]+red[3]) * (1.f/FD);
    __syncthreads();
    float dv = t - mu;
    float v = dv*dv;
    #pragma unroll
    for (int o = 16; o; o >>= 1) v += __shfl_xor_sync(0xffffffffu, v, o);
    if ((j & 31) == 0) red[j >> 5] = v;
    __syncthreads();
    float var = (red[0]+red[1]+red[2]+red[3]) * (1.f/FD);
    outA[(size_t)i*FD + j] = dv * rsqrtf(var + 1e-5f) * lng[j] + lnb[j];
}

// ---------------- launch ----------------
extern "C" void kernel_launch(void* const* d_in, const int* in_sizes, int n_in,
                              void* d_out, int out_size){
    const float* atom  = (const float*)d_in[0];
    const float* force = (const float*)d_in[1];
    const float* disp  = (const float*)d_in[2];
    const float* dispe = (const float*)d_in[3];
    const float* dist  = (const float*)d_in[4];
    const int*   eidx  = (const int*)  d_in[5];
    const float* nW1 = (const float*)d_in[6],  *nb1 = (const float*)d_in[7];
    const float* nW2 = (const float*)d_in[8],  *nb2 = (const float*)d_in[9];
    const float* eW  = (const float*)d_in[10], *eb  = (const float*)d_in[11];
    const float* q1W1= (const float*)d_in[12], *q1b1= (const float*)d_in[13];
    const float* q1W2= (const float*)d_in[14], *q1b2= (const float*)d_in[15];
    const float* q2W1= (const float*)d_in[16], *q2b1= (const float*)d_in[17];
    const float* q2W2= (const float*)d_in[18], *q2b2= (const float*)d_in[19];
    const float* q3W1= (const float*)d_in[20], *q3W2= (const float*)d_in[21];
    const float* uW1 = (const float*)d_in[22], *ub1 = (const float*)d_in[23];
    const float* uW2 = (const float*)d_in[24], *ub2 = (const float*)d_in[25];
    const float* lng = (const float*)d_in[26], *lnb = (const float*)d_in[27];

    float* out  = (float*)d_out;
    float* outA = out;
    float* outF = out + NF;
    float* outD = out + NF + N3F;

    float *pH, *pMSG, *pAGG, *pATOM, *pEQ3, *pU;
    cudaGetSymbolAddress((void**)&pH,    g_H);
    cudaGetSymbolAddress((void**)&pMSG,  g_MSG);
    cudaGetSymbolAddress((void**)&pAGG,  g_AGG1);
    cudaGetSymbolAddress((void**)&pATOM, g_ATOM);
    cudaGetSymbolAddress((void**)&pEQ3,  g_EQ3);
    cudaGetSymbolAddress((void**)&pU,    g_U);
    __nv_bfloat16* pWP;
    cudaGetSymbolAddress((void**)&pWP, g_WP);

    cudaFuncSetAttribute(mlp2_ws<0>, cudaFuncAttributeMaxDynamicSharedMemorySize, SMEM_TOT);
    cudaFuncSetAttribute(mlp2_ws<2>, cudaFuncAttributeMaxDynamicSharedMemorySize, SMEM_TOT);
    cudaFuncSetAttribute(mlp2_ws<3>, cudaFuncAttributeMaxDynamicSharedMemorySize, SMEM_TOT);
    cudaFuncSetAttribute(mlp2_ws<4>, cudaFuncAttributeMaxDynamicSharedMemorySize, SMEM_T4);

    const int NODE_GRID = (NN + TROWS - 1) / TROWS;   // 157
    const int EDGE_GRID = 444;                         // 3 CTAs/SM

    WPtrs P;
    P.w[0]=nW1; P.w[1]=nW2; P.w[2]=q1W1; P.w[3]=q1W2; P.w[4]=q2W1;
    P.w[5]=q2W2; P.w[6]=q3W1; P.w[7]=q3W2; P.w[8]=uW1; P.w[9]=uW2;
    P.w[10]=eW;

    // 0. pre-split all weights (incl. empW) into bf16 hi/lo blocks
    prep_w<<<81, 256>>>(P);
    // 1. init accumulation buffers
    init_kernel<<<N3F/4/256, 256>>>(atom, force, disp, out);
    // 2. h = mlp2(atom, nmp)
    mlp2_ws<0><<<NODE_GRID, 128, SMEM_TOT>>>(atom, NN, pWP + 0*WMAT_BF, pWP + 1*WMAT_BF,
                                             nb1, nb2, pH, nullptr, nullptr, nullptr, nullptr,
                                             nullptr);
    // 3+4. FUSED: edge message (tensor-core E; msg -> g_MSG, red4 -> g_ATOM) + eq1 scatter
    mlp2_ws<4><<<EDGE_GRID, 128, SMEM_T4>>>(nullptr, NE, pWP + 2*WMAT_BF, pWP + 3*WMAT_BF,
                                            q1b1, q1b2, pMSG, eidx, dispe, dist, pAGG,
                                            eb);
    // 5. eq2: mlp2(msg) * disp_node[dst] -> out_disp
    mlp2_ws<2><<<EDGE_GRID, 128, SMEM_TOT>>>(pMSG, NE, pWP + 4*WMAT_BF, pWP + 5*WMAT_BF,
                                             q2b1, q2b2, nullptr, eidx, nullptr, disp, outD,
                                             nullptr);
    // 6. force_out = force + agg1
    force_add_kernel<<<(N3F/4 + 255)/256, 256>>>(outF);
    // 7. eq3_inv = mlp2_nobias(atom_new, eq3)
    mlp2_ws<3><<<NODE_GRID, 128, SMEM_TOT>>>(pATOM, NN, pWP + 6*WMAT_BF, pWP + 7*WMAT_BF,
                                             nullptr, nullptr, pEQ3, nullptr, nullptr, nullptr, nullptr,
                                             nullptr);
    // 8. eq3 scatter
    eq3_edge_kernel<<<800, 256>>>(eidx, outD);
    // 9. u = mlp2(atom_new, upd)
    mlp2_ws<0><<<NODE_GRID, 128, SMEM_TOT>>>(pATOM, NN, pWP + 8*WMAT_BF, pWP + 9*WMAT_BF,
                                             ub1, ub2, pU, nullptr, nullptr, nullptr, nullptr,
                                             nullptr);
    // 10. inv_update coupling + layernorm
    final_kernel<<<NN, 128>>>(outF, outD, lng, lnb, outA);
}

// round 13
// speedup vs baseline: 1.0352x; 1.0352x over previous
#include <cuda_runtime.h>
#include <cuda_bf16.h>
#include <math.h>
#include <stdint.h>
#include <mma.h>

using namespace nvcuda;

#define NN 10000
#define NE 200000
#define FD 128
#define NBD 20
#define NF (NN*FD)
#define N3F (NN*3*FD)
#define LDB 136          // bf16 tile leading dim
#define SCRLD 20         // fp32 scratch leading dim
#define TROWS 64         // rows per CTA tile

// byte offsets inside dynamic SMEM (per 128-thread CTA)
#define OFF_AH   0                 // 64 x 136 bf16 = 17408
#define OFF_AL   17408
#define OFF_WB   34816             // 2 weight-slice buffers x 8704 B
#define OFF_SCR  52224             // 4 warps x 16*20*4 = 5120
#define OFF_B1   57344
#define OFF_B2   57856
#define SMEM_TOT 58368
// EPI4 (fused edge-message) extras
#define OFF_EW   58368             // empW 20x128 fp32 = 10240
#define OFF_EB   68608             // empb 512
#define SMEM_T4  69120

#define WSLICE_BF 4352             // bf16 per k-slice block (H 16x136 + L 16x136)
#define WMAT_BF  (8*WSLICE_BF)     // bf16 per prepared matrix

// ---------------- scratch (device globals; no allocation) ----------------
__device__ float g_H[NF];
__device__ float g_MSG[NE*FD];
__device__ float g_AGG1[N3F];
__device__ float g_ATOM[NF];
__device__ float g_EQ3[NF];
__device__ float g_U[NF];
__device__ __nv_bfloat16 g_WP[10*WMAT_BF];   // pre-split weights (hi/lo k-slices)

// ---------------- helpers ----------------
__device__ __forceinline__ float4 ld4(const float* p){ return *reinterpret_cast<const float4*>(p); }
__device__ __forceinline__ void st4(float* p, float4 v){ *reinterpret_cast<float4*>(p) = v; }
__device__ __forceinline__ float silu_f(float x){ return x * (1.0f/(1.0f + __expf(-x))); }
__device__ __forceinline__ void red4(float* p, float4 v){
    asm volatile("red.global.add.v4.f32 [%0], {%1,%2,%3,%4};"
        :: "l"(p), "f"(v.x), "f"(v.y), "f"(v.z), "f"(v.w) : "memory");
}
__device__ __forceinline__ uint32_t packbf2(float a, float b){
    __nv_bfloat162 t = __floats2bfloat162_rn(a, b);
    return *reinterpret_cast<uint32_t*>(&t);
}
__device__ __forceinline__ float bf2f(uint32_t u, int half){
    __nv_bfloat162 t = *reinterpret_cast<__nv_bfloat162*>(&u);
    return half ? __bfloat162float(__high2bfloat16(t)) : __bfloat162float(__low2bfloat16(t));
}
__device__ __forceinline__ void cpasync16(uint32_t saddr, const void* gaddr){
    asm volatile("cp.async.cg.shared.global [%0], [%1], 16;" :: "r"(saddr), "l"(gaddr) : "memory");
}
__device__ __forceinline__ void cpcommit(){
    asm volatile("cp.async.commit_group;" ::: "memory");
}
template<int N> __device__ __forceinline__ void cpwait(){
    asm volatile("cp.async.wait_group %0;" :: "n"(N) : "memory");
}

// split x into hi(bf16) + lo(bf16 of residual); write 4 cols (8B) to each tile
__device__ __forceinline__ void split_store4(char* sb, int offH, int offL,
                                             int row, int col, float4 v){
    uint32_t h0 = packbf2(v.x, v.y);
    uint32_t h1 = packbf2(v.z, v.w);
    float4 r;
    r.x = v.x - bf2f(h0,0); r.y = v.y - bf2f(h0,1);
    r.z = v.z - bf2f(h1,0); r.w = v.w - bf2f(h1,1);
    uint32_t l0 = packbf2(r.x, r.y);
    uint32_t l1 = packbf2(r.z, r.w);
    uint2 hh; hh.x = h0; hh.y = h1;
    uint2 ll; ll.x = l0; ll.y = l1;
    *reinterpret_cast<uint2*>(sb + offH + (row*LDB + col)*2) = hh;
    *reinterpret_cast<uint2*>(sb + offL + (row*LDB + col)*2) = ll;
}

// ---------------- weight prep: fp32 [k][c] -> bf16 hi/lo k-slice blocks ----------------
struct WPtrs { const float* w[10]; };

__global__ void prep_w(WPtrs P){
    int m  = blockIdx.x >> 3;
    int ks = blockIdx.x & 7;
    const float* W = P.w[m];
    __nv_bfloat16* dst = g_WP + m*WMAT_BF + ks*WSLICE_BF;
    for (int e = threadIdx.x; e < 16*FD; e += blockDim.x){
        int kr = e >> 7, c = e & 127;
        float w = W[(ks*16 + kr)*FD + c];
        __nv_bfloat16 h = __float2bfloat16_rn(w);
        __nv_bfloat16 l = __float2bfloat16_rn(w - __bfloat162float(h));
        dst[kr*LDB + c]        = h;
        dst[2176 + kr*LDB + c] = l;
    }
}

// ---------------- init ----------------
__global__ void init_kernel(const float* __restrict__ atom, const float* __restrict__ force,
                            const float* __restrict__ disp, float* __restrict__ out){
    int i = blockIdx.x*blockDim.x + threadIdx.x;
    if (i < N3F/4) {
        ((float4*)(out + NF))[i]        = ((const float4*)force)[i];
        ((float4*)(out + NF + N3F))[i]  = ((const float4*)disp)[i];
        ((float4*)g_AGG1)[i]            = make_float4(0.f,0.f,0.f,0.f);
    }
    if (i < NF/4) ((float4*)g_ATOM)[i] = ((const float4*)atom)[i];
}

// ---------------- bf16x3 wmma fused 2-layer MLP, weight-streaming ----------------
// 128 threads, 64-row tiles, warp block 32x64, 3 CTAs/SM.
// EPI 0: Y with biases   EPI 3: Y no-bias
// EPI 2: red(accout[src,d,:], m * disp_node[dst,d,:])
// EPI 4: eq1 with fused edge message: prologue computes
//        e = dist@empW + b; msg = e*h[src]*h[dst]; writes msg to Y (=g_MSG),
//        red4s msg into g_ATOM, splits msg into A tiles. `dispn` carries dist.
template<int EPI>
__global__ void __launch_bounds__(128,3)
mlp2_ws(const float* __restrict__ X, int nrows,
        const __nv_bfloat16* __restrict__ w1, const __nv_bfloat16* __restrict__ w2,
        const float* __restrict__ b1, const float* __restrict__ b2,
        float* __restrict__ Y,
        const int* __restrict__ eidx, const float* __restrict__ dispe,
        const float* __restrict__ dispn, float* __restrict__ accout,
        const float* __restrict__ empW, const float* __restrict__ empb)
{
    extern __shared__ char sb[];
    float* sB1 = (float*)(sb + OFF_B1);
    float* sB2 = (float*)(sb + OFF_B2);

    const int tid  = threadIdx.x;
    const int wid  = tid >> 5;       // 4 warps
    const int lane = tid & 31;

    sB1[tid] = b1 ? b1[tid] : 0.f;
    sB2[tid] = b2 ? b2[tid] : 0.f;

    if (EPI == 4){
        float* sEW = (float*)(sb + OFF_EW);
        float* sEB = (float*)(sb + OFF_EB);
        for (int i = tid; i < NBD*FD; i += 128) sEW[i] = empW[i];
        if (tid < FD) sEB[tid] = empb[tid];
    }
    __syncthreads();

    const __nv_bfloat16* pAH = (const __nv_bfloat16*)(sb + OFF_AH);
    const __nv_bfloat16* pAL = (const __nv_bfloat16*)(sb + OFF_AL);
    float* scr = (float*)(sb + OFF_SCR) + wid*16*SCRLD;
    const uint32_t wb0 = (uint32_t)__cvta_generic_to_shared(sb + OFF_WB);

    const int ntiles = (nrows + TROWS - 1) / TROWS;
    const int pr = wid >> 1;            // pair (row group) 0..1
    const int sub = wid & 1;            // column half
    const int wr = pr * 32;
    const int wc = sub * 64;
    const int lr = lane >> 1;           // 0..15
    const int lc = (lane & 1) * 8;      // 0 or 8

    auto copy_slice = [&](int buf, const __nv_bfloat16* src){
        uint32_t dst = wb0 + buf*8704;
        const char* s = (const char*)src;
        #pragma unroll
        for (int j = 0; j < 5; j++){
            int idx = tid + j*128;
            if (idx < 544) cpasync16(dst + idx*16, s + idx*16);
        }
    };

    for (int tile = blockIdx.x; tile < ntiles; tile += gridDim.x){
        const int row0 = tile * TROWS;

        if (EPI == 4){
            // ---- compute 16 edge messages per warp, split hi/lo into A tiles ----
            const float* sEW = (const float*)(sb + OFF_EW);
            const float* sEB = (const float*)(sb + OFF_EB);
            #pragma unroll 2
            for (int rr = 0; rr < 16; rr++){
                int rl = wid*16 + rr;
                int e  = row0 + rl;
                float4 m = make_float4(0.f,0.f,0.f,0.f);
                if (e < nrows){
                    int s = __ldg(eidx + e);
                    int t = __ldg(eidx + NE + e);
                    float4 a = ld4(sEB + lane*4);
                    #pragma unroll
                    for (int nb = 0; nb < NBD; nb++){
                        float d  = __ldg(dispn + (size_t)e*NBD + nb);   // dispn = dist
                        float4 w = ld4(sEW + nb*FD + lane*4);
                        a.x = fmaf(d, w.x, a.x);
                        a.y = fmaf(d, w.y, a.y);
                        a.z = fmaf(d, w.z, a.z);
                        a.w = fmaf(d, w.w, a.w);
                    }
                    float4 hs = ld4(g_H + (size_t)s*FD + lane*4);
                    float4 ht = ld4(g_H + (size_t)t*FD + lane*4);
                    m = make_float4(a.x*hs.x*ht.x, a.y*hs.y*ht.y,
                                    a.z*hs.z*ht.z, a.w*hs.w*ht.w);
                    st4(Y + (size_t)e*FD + lane*4, m);                  // Y = g_MSG
                    red4(g_ATOM + (size_t)s*FD + lane*4, m);
                }
                split_store4(sb, OFF_AH, OFF_AL, rl, lane*4, m);
            }
        } else {
            #pragma unroll 4
            for (int rr = 0; rr < 16; rr++){
                int rl  = wid*16 + rr;
                int row = row0 + rl;
                float4 v = make_float4(0.f,0.f,0.f,0.f);
                if (row < nrows) v = ld4(X + (size_t)row*FD + lane*4);
                split_store4(sb, OFF_AH, OFF_AL, rl, lane*4, v);
            }
        }

        copy_slice(0, w1); cpcommit();

        wmma::fragment<wmma::accumulator,16,16,16,float> acc[2][4];
        #pragma unroll
        for (int p = 0; p < 2; p++)
            #pragma unroll
            for (int ct = 0; ct < 4; ct++) wmma::fill_fragment(acc[p][ct], 0.f);

        // ================= stage 1: D = X @ W1 (bf16x3) =================
        #pragma unroll
        for (int ks = 0; ks < 8; ks++){
            if (ks < 7) copy_slice((ks+1)&1, w1 + (ks+1)*WSLICE_BF);
            else        copy_slice(0,        w2);
            cpcommit();
            cpwait<1>();
            __syncthreads();
            {
                const __nv_bfloat16* bufH = (const __nv_bfloat16*)(sb + OFF_WB + (ks&1)*8704);
                const __nv_bfloat16* bufL = bufH + 2176;
                wmma::fragment<wmma::matrix_a,16,16,16,__nv_bfloat16,wmma::row_major> aH[2], aL[2];
                #pragma unroll
                for (int p = 0; p < 2; p++){
                    wmma::load_matrix_sync(aH[p], pAH + (wr + p*16)*LDB + ks*16, LDB);
                    wmma::load_matrix_sync(aL[p], pAL + (wr + p*16)*LDB + ks*16, LDB);
                }
                #pragma unroll
                for (int ct = 0; ct < 4; ct++){
                    wmma::fragment<wmma::matrix_b,16,16,16,__nv_bfloat16,wmma::row_major> bH, bL;
                    wmma::load_matrix_sync(bH, bufH + wc + ct*16, LDB);
                    wmma::load_matrix_sync(bL, bufL + wc + ct*16, LDB);
                    #pragma unroll
                    for (int p = 0; p < 2; p++){
                        wmma::mma_sync(acc[p][ct], aH[p], bL, acc[p][ct]);
                        wmma::mma_sync(acc[p][ct], aL[p], bH, acc[p][ct]);
                        wmma::mma_sync(acc[p][ct], aH[p], bH, acc[p][ct]);
                    }
                }
            }
            __syncthreads();
        }

        // ---- silu(d + b1), re-split into A tiles ----
        #pragma unroll
        for (int p = 0; p < 2; p++){
            #pragma unroll
            for (int ct = 0; ct < 4; ct++){
                wmma::store_matrix_sync(scr, acc[p][ct], SCRLD, wmma::mem_row_major);
                __syncwarp();
                int c0 = wc + ct*16 + lc;
                float4 v0 = ld4(scr + lr*SCRLD + lc);
                float4 v1 = ld4(scr + lr*SCRLD + lc + 4);
                float4 bb0 = ld4(sB1 + c0);
                float4 bb1 = ld4(sB1 + c0 + 4);
                v0.x = silu_f(v0.x + bb0.x); v0.y = silu_f(v0.y + bb0.y);
                v0.z = silu_f(v0.z + bb0.z); v0.w = silu_f(v0.w + bb0.w);
                v1.x = silu_f(v1.x + bb1.x); v1.y = silu_f(v1.y + bb1.y);
                v1.z = silu_f(v1.z + bb1.z); v1.w = silu_f(v1.w + bb1.w);
                split_store4(sb, OFF_AH, OFF_AL, wr + p*16 + lr, c0,     v0);
                split_store4(sb, OFF_AH, OFF_AL, wr + p*16 + lr, c0 + 4, v1);
                __syncwarp();
            }
        }

        #pragma unroll
        for (int p = 0; p < 2; p++)
            #pragma unroll
            for (int ct = 0; ct < 4; ct++) wmma::fill_fragment(acc[p][ct], 0.f);

        // ================= stage 2: D = H @ W2 (bf16x3) =================
        #pragma unroll
        for (int ks = 0; ks < 8; ks++){
            if (ks < 7){ copy_slice((ks+1)&1, w2 + (ks+1)*WSLICE_BF); cpcommit(); cpwait<1>(); }
            else       { cpwait<0>(); }
            __syncthreads();
            {
                const __nv_bfloat16* bufH = (const __nv_bfloat16*)(sb + OFF_WB + (ks&1)*8704);
                const __nv_bfloat16* bufL = bufH + 2176;
                wmma::fragment<wmma::matrix_a,16,16,16,__nv_bfloat16,wmma::row_major> aH[2], aL[2];
                #pragma unroll
                for (int p = 0; p < 2; p++){
                    wmma::load_matrix_sync(aH[p], pAH + (wr + p*16)*LDB + ks*16, LDB);
                    wmma::load_matrix_sync(aL[p], pAL + (wr + p*16)*LDB + ks*16, LDB);
                }
                #pragma unroll
                for (int ct = 0; ct < 4; ct++){
                    wmma::fragment<wmma::matrix_b,16,16,16,__nv_bfloat16,wmma::row_major> bH, bL;
                    wmma::load_matrix_sync(bH, bufH + wc + ct*16, LDB);
                    wmma::load_matrix_sync(bL, bufL + wc + ct*16, LDB);
                    #pragma unroll
                    for (int p = 0; p < 2; p++){
                        wmma::mma_sync(acc[p][ct], aH[p], bL, acc[p][ct]);
                        wmma::mma_sync(acc[p][ct], aL[p], bH, acc[p][ct]);
                        wmma::mma_sync(acc[p][ct], aH[p], bH, acc[p][ct]);
                    }
                }
            }
            __syncthreads();
        }

        // ================= epilogue =================
        #pragma unroll
        for (int p = 0; p < 2; p++){
            const int row = row0 + wr + p*16 + lr;
            const bool valid = (row < nrows);
            int s = 0, t = 0;
            float d0 = 0.f, d1 = 0.f, d2 = 0.f;
            if (EPI == 4 && valid){
                s = __ldg(eidx + row);
                d0 = __ldg(dispe + (size_t)row*3 + 0);
                d1 = __ldg(dispe + (size_t)row*3 + 1);
                d2 = __ldg(dispe + (size_t)row*3 + 2);
            }
            if (EPI == 2 && valid){
                s = __ldg(eidx + row);
                t = __ldg(eidx + NE + row);
            }
            #pragma unroll
            for (int ct = 0; ct < 4; ct++){
                wmma::store_matrix_sync(scr, acc[p][ct], SCRLD, wmma::mem_row_major);
                __syncwarp();
                if (valid){
                    int c0 = wc + ct*16 + lc;
                    float4 m0 = ld4(scr + lr*SCRLD + lc);
                    float4 m1 = ld4(scr + lr*SCRLD + lc + 4);
                    float4 bb0 = ld4(sB2 + c0);
                    float4 bb1 = ld4(sB2 + c0 + 4);
                    m0.x += bb0.x; m0.y += bb0.y; m0.z += bb0.z; m0.w += bb0.w;
                    m1.x += bb1.x; m1.y += bb1.y; m1.z += bb1.z; m1.w += bb1.w;

                    if (EPI == 0 || EPI == 3){
                        st4(Y + (size_t)row*FD + c0,     m0);
                        st4(Y + (size_t)row*FD + c0 + 4, m1);
                    } else if (EPI == 4){
                        float* bp = accout + (size_t)s*3*FD + c0;
                        red4(bp,            make_float4(m0.x*d0, m0.y*d0, m0.z*d0, m0.w*d0));
                        red4(bp + 4,        make_float4(m1.x*d0, m1.y*d0, m1.z*d0, m1.w*d0));
                        red4(bp + FD,       make_float4(m0.x*d1, m0.y*d1, m0.z*d1, m0.w*d1));
                        red4(bp + FD + 4,   make_float4(m1.x*d1, m1.y*d1, m1.z*d1, m1.w*d1));
                        red4(bp + 2*FD,     make_float4(m0.x*d2, m0.y*d2, m0.z*d2, m0.w*d2));
                        red4(bp + 2*FD + 4, make_float4(m1.x*d2, m1.y*d2, m1.z*d2, m1.w*d2));
                    } else { // EPI == 2
                        const float* gp = dispn + (size_t)t*3*FD + c0;
                        float* bp = accout + (size_t)s*3*FD + c0;
                        #pragma unroll
                        for (int d = 0; d < 3; d++){
                            float4 g0 = ld4(gp + d*FD);
                            float4 g1 = ld4(gp + d*FD + 4);
                            red4(bp + d*FD,     make_float4(m0.x*g0.x, m0.y*g0.y, m0.z*g0.z, m0.w*g0.w));
                            red4(bp + d*FD + 4, make_float4(m1.x*g1.x, m1.y*g1.y, m1.z*g1.z, m1.w*g1.w));
                        }
                    }
                }
                __syncwarp();
            }
        }
        __syncthreads();
    }
}

// ---------------- force_out += agg1 ----------------
__global__ void force_add_kernel(float* __restrict__ outF){
    int i = blockIdx.x*blockDim.x + threadIdx.x;
    if (i < N3F/4){
        float4 a = ((float4*)g_AGG1)[i];
        float4 f = ((float4*)outF)[i];
        ((float4*)outF)[i] = make_float4(f.x+a.x, f.y+a.y, f.z+a.z, f.w+a.w);
    }
}

// ---------------- eq3: disp[src] += eq3_inv[dst] * agg1[dst] ----------------
__global__ void eq3_edge_kernel(const int* __restrict__ eidx, float* __restrict__ out_disp){
    const int tid  = threadIdx.x;
    const int lane = tid & 31;
    const int warp = (blockIdx.x*blockDim.x + tid) >> 5;
    const int nw   = (gridDim.x*blockDim.x) >> 5;
    for (int e = warp; e < NE; e += nw) {
        int s = __ldg(eidx + e);
        int t = __ldg(eidx + NE + e);
        float4 g = ld4(g_EQ3 + (size_t)t*FD + lane*4);
        #pragma unroll
        for (int d = 0; d < 3; d++) {
            float4 a = ld4(g_AGG1 + ((size_t)t*3 + d)*FD + lane*4);
            red4(out_disp + ((size_t)s*3 + d)*FD + lane*4,
                 make_float4(g.x*a.x, g.y*a.y, g.z*a.z, g.w*a.w));
        }
    }
}

// ---------------- final: inv_update + layernorm ----------------
__global__ void final_kernel(const float* __restrict__ outF, const float* __restrict__ outD,
                             const float* __restrict__ lng, const float* __restrict__ lnb,
                             float* __restrict__ outA){
    const int i = blockIdx.x;
    const int j = threadIdx.x;   // 128
    float c = 0.f;
    #pragma unroll
    for (int d = 0; d < 3; d++)
        c -= outF[((size_t)i*3 + d)*FD + j] * outD[((size_t)i*3 + d)*FD + j];
    float t = g_ATOM[(size_t)i*FD + j] + g_U[(size_t)i*FD + j] * c;

    __shared__ float red[4];
    float s = t;
    #pragma unroll
    for (int o = 16; o; o >>= 1) s += __shfl_xor_sync(0xffffffffu, s, o);
    if ((j & 31) == 0) red[j >> 5] = s;
    __syncthreads();
    float mu = (red[0]+red[1]+red[2]+red[3]) * (1.f/FD);
    __syncthreads();
    float dv = t - mu;
    float v = dv*dv;
    #pragma unroll
    for (int o = 16; o; o >>= 1) v += __shfl_xor_sync(0xffffffffu, v, o);
    if ((j & 31) == 0) red[j >> 5] = v;
    __syncthreads();
    float var = (red[0]+red[1]+red[2]+red[3]) * (1.f/FD);
    outA[(size_t)i*FD + j] = dv * rsqrtf(var + 1e-5f) * lng[j] + lnb[j];
}

// ---------------- launch ----------------
extern "C" void kernel_launch(void* const* d_in, const int* in_sizes, int n_in,
                              void* d_out, int out_size){
    const float* atom  = (const float*)d_in[0];
    const float* force = (const float*)d_in[1];
    const float* disp  = (const float*)d_in[2];
    const float* dispe = (const float*)d_in[3];
    const float* dist  = (const float*)d_in[4];
    const int*   eidx  = (const int*)  d_in[5];
    const float* nW1 = (const float*)d_in[6],  *nb1 = (const float*)d_in[7];
    const float* nW2 = (const float*)d_in[8],  *nb2 = (const float*)d_in[9];
    const float* eW  = (const float*)d_in[10], *eb  = (const float*)d_in[11];
    const float* q1W1= (const float*)d_in[12], *q1b1= (const float*)d_in[13];
    const float* q1W2= (const float*)d_in[14], *q1b2= (const float*)d_in[15];
    const float* q2W1= (const float*)d_in[16], *q2b1= (const float*)d_in[17];
    const float* q2W2= (const float*)d_in[18], *q2b2= (const float*)d_in[19];
    const float* q3W1= (const float*)d_in[20], *q3W2= (const float*)d_in[21];
    const float* uW1 = (const float*)d_in[22], *ub1 = (const float*)d_in[23];
    const float* uW2 = (const float*)d_in[24], *ub2 = (const float*)d_in[25];
    const float* lng = (const float*)d_in[26], *lnb = (const float*)d_in[27];

    float* out  = (float*)d_out;
    float* outA = out;
    float* outF = out + NF;
    float* outD = out + NF + N3F;

    float *pH, *pMSG, *pAGG, *pATOM, *pEQ3, *pU;
    cudaGetSymbolAddress((void**)&pH,    g_H);
    cudaGetSymbolAddress((void**)&pMSG,  g_MSG);
    cudaGetSymbolAddress((void**)&pAGG,  g_AGG1);
    cudaGetSymbolAddress((void**)&pATOM, g_ATOM);
    cudaGetSymbolAddress((void**)&pEQ3,  g_EQ3);
    cudaGetSymbolAddress((void**)&pU,    g_U);
    __nv_bfloat16* pWP;
    cudaGetSymbolAddress((void**)&pWP, g_WP);

    cudaFuncSetAttribute(mlp2_ws<0>, cudaFuncAttributeMaxDynamicSharedMemorySize, SMEM_TOT);
    cudaFuncSetAttribute(mlp2_ws<2>, cudaFuncAttributeMaxDynamicSharedMemorySize, SMEM_TOT);
    cudaFuncSetAttribute(mlp2_ws<3>, cudaFuncAttributeMaxDynamicSharedMemorySize, SMEM_TOT);
    cudaFuncSetAttribute(mlp2_ws<4>, cudaFuncAttributeMaxDynamicSharedMemorySize, SMEM_T4);

    const int NODE_GRID = (NN + TROWS - 1) / TROWS;   // 157
    const int EDGE_GRID = 444;                         // 3 CTAs/SM

    WPtrs P;
    P.w[0]=nW1; P.w[1]=nW2; P.w[2]=q1W1; P.w[3]=q1W2; P.w[4]=q2W1;
    P.w[5]=q2W2; P.w[6]=q3W1; P.w[7]=q3W2; P.w[8]=uW1; P.w[9]=uW2;

    // side stream + fork/join events (created once; host-side resources only —
    // the captured GPU work is identical on every call)
    static cudaStream_t sB = nullptr;
    static cudaEvent_t evF0, evJ0, evF1, evJ1;
    if (sB == nullptr){
        cudaStreamCreateWithFlags(&sB, cudaStreamNonBlocking);
        cudaEventCreateWithFlags(&evF0, cudaEventDisableTiming);
        cudaEventCreateWithFlags(&evJ0, cudaEventDisableTiming);
        cudaEventCreateWithFlags(&evF1, cudaEventDisableTiming);
        cudaEventCreateWithFlags(&evJ1, cudaEventDisableTiming);
    }

    // ---- fork 0: init (side) || prep_w + h-MLP (main) ----
    cudaEventRecord(evF0, 0);
    cudaStreamWaitEvent(sB, evF0, 0);
    init_kernel<<<N3F/4/256, 256, 0, sB>>>(atom, force, disp, out);

    prep_w<<<80, 256>>>(P);
    mlp2_ws<0><<<NODE_GRID, 128, SMEM_TOT>>>(atom, NN, pWP + 0*WMAT_BF, pWP + 1*WMAT_BF,
                                             nb1, nb2, pH, nullptr, nullptr, nullptr, nullptr,
                                             nullptr, nullptr);
    cudaEventRecord(evJ0, sB);
    cudaStreamWaitEvent(0, evJ0, 0);

    // ---- fused eq1: edge message (msg -> g_MSG, red4 -> g_ATOM) + eq1 scatter -> agg1 ----
    mlp2_ws<4><<<EDGE_GRID, 128, SMEM_T4>>>(nullptr, NE, pWP + 2*WMAT_BF, pWP + 3*WMAT_BF,
                                            q1b1, q1b2, pMSG, eidx, dispe, dist, pAGG,
                                            eW, eb);

    // ---- fork 1: eq2 (side) || force_add + eq3-chain + upd-MLP (main) ----
    cudaEventRecord(evF1, 0);
    cudaStreamWaitEvent(sB, evF1, 0);
    mlp2_ws<2><<<EDGE_GRID, 128, SMEM_TOT, sB>>>(pMSG, NE, pWP + 4*WMAT_BF, pWP + 5*WMAT_BF,
                                                 q2b1, q2b2, nullptr, eidx, nullptr, disp, outD,
                                                 nullptr, nullptr);

    force_add_kernel<<<(N3F/4 + 255)/256, 256>>>(outF);
    mlp2_ws<3><<<NODE_GRID, 128, SMEM_TOT>>>(pATOM, NN, pWP + 6*WMAT_BF, pWP + 7*WMAT_BF,
                                             nullptr, nullptr, pEQ3, nullptr, nullptr, nullptr, nullptr,
                                             nullptr, nullptr);
    eq3_edge_kernel<<<800, 256>>>(eidx, outD);
    mlp2_ws<0><<<NODE_GRID, 128, SMEM_TOT>>>(pATOM, NN, pWP + 8*WMAT_BF, pWP + 9*WMAT_BF,
                                             ub1, ub2, pU, nullptr, nullptr, nullptr, nullptr,
                                             nullptr, nullptr);
    cudaEventRecord(evJ1, sB);
    cudaStreamWaitEvent(0, evJ1, 0);

    // ---- join: inv_update coupling + layernorm ----
    final_kernel<<<NN, 128>>>(outF, outD, lng, lnb, outA);
}

// round 14
// speedup vs baseline: 1.0793x; 1.0426x over previous
#include <cuda_runtime.h>
#include <cuda_bf16.h>
#include <math.h>
#include <stdint.h>
#include <mma.h>

using namespace nvcuda;

#define NN 10000
#define NE 200000
#define FD 128
#define NBD 20
#define NF (NN*FD)
#define N3F (NN*3*FD)
#define LDB 136          // bf16 tile leading dim
#define SCRLD 20         // fp32 scratch leading dim
#define TROWS 64         // rows per CTA tile

// byte offsets inside dynamic SMEM (per 128-thread CTA)
#define OFF_AH   0                 // 64 x 136 bf16 = 17408
#define OFF_AL   17408
#define OFF_WB   34816             // 2 weight-slice buffers x 8704 B
#define OFF_SCR  52224             // 4 warps x 16*20*4 = 5120
#define OFF_B1   57344
#define OFF_B2   57856
#define SMEM_TOT 58368
// EPI4 (fused edge-message) extras
#define OFF_EW   58368             // empW 20x128 fp32 = 10240
#define OFF_EB   68608             // empb 512
#define SMEM_T4  69120

#define WSLICE_BF 4352             // bf16 per k-slice block (H 16x136 + L 16x136)
#define WMAT_BF  (8*WSLICE_BF)     // bf16 per prepared matrix

// ---------------- scratch (device globals; no allocation) ----------------
__device__ float g_H[NF];
__device__ float g_MSG[NE*FD];
__device__ float g_AGG1[N3F];
__device__ float g_ATOM[NF];
__device__ float g_EQ3[NF];
__device__ float g_U[NF];
__device__ __nv_bfloat16 g_WP[10*WMAT_BF];   // pre-split weights (hi/lo k-slices)

// ---------------- helpers ----------------
__device__ __forceinline__ float4 ld4(const float* p){ return *reinterpret_cast<const float4*>(p); }
__device__ __forceinline__ void st4(float* p, float4 v){ *reinterpret_cast<float4*>(p) = v; }
__device__ __forceinline__ float silu_f(float x){ return x * (1.0f/(1.0f + __expf(-x))); }
__device__ __forceinline__ void red4(float* p, float4 v){
    asm volatile("red.global.add.v4.f32 [%0], {%1,%2,%3,%4};"
        :: "l"(p), "f"(v.x), "f"(v.y), "f"(v.z), "f"(v.w) : "memory");
}
__device__ __forceinline__ uint32_t packbf2(float a, float b){
    __nv_bfloat162 t = __floats2bfloat162_rn(a, b);
    return *reinterpret_cast<uint32_t*>(&t);
}
__device__ __forceinline__ float bf2f(uint32_t u, int half){
    __nv_bfloat162 t = *reinterpret_cast<__nv_bfloat162*>(&u);
    return half ? __bfloat162float(__high2bfloat16(t)) : __bfloat162float(__low2bfloat16(t));
}
__device__ __forceinline__ void cpasync16(uint32_t saddr, const void* gaddr){
    asm volatile("cp.async.cg.shared.global [%0], [%1], 16;" :: "r"(saddr), "l"(gaddr) : "memory");
}
__device__ __forceinline__ void cpcommit(){
    asm volatile("cp.async.commit_group;" ::: "memory");
}
template<int N> __device__ __forceinline__ void cpwait(){
    asm volatile("cp.async.wait_group %0;" :: "n"(N) : "memory");
}

// split x into hi(bf16) + lo(bf16 of residual); write 4 cols (8B) to each tile
__device__ __forceinline__ void split_store4(char* sb, int offH, int offL,
                                             int row, int col, float4 v){
    uint32_t h0 = packbf2(v.x, v.y);
    uint32_t h1 = packbf2(v.z, v.w);
    float4 r;
    r.x = v.x - bf2f(h0,0); r.y = v.y - bf2f(h0,1);
    r.z = v.z - bf2f(h1,0); r.w = v.w - bf2f(h1,1);
    uint32_t l0 = packbf2(r.x, r.y);
    uint32_t l1 = packbf2(r.z, r.w);
    uint2 hh; hh.x = h0; hh.y = h1;
    uint2 ll; ll.x = l0; ll.y = l1;
    *reinterpret_cast<uint2*>(sb + offH + (row*LDB + col)*2) = hh;
    *reinterpret_cast<uint2*>(sb + offL + (row*LDB + col)*2) = ll;
}

// ---------------- weight prep: fp32 [k][c] -> bf16 hi/lo k-slice blocks ----------------
struct WPtrs { const float* w[10]; };

__global__ void prep_w(WPtrs P){
    int m  = blockIdx.x >> 3;
    int ks = blockIdx.x & 7;
    const float* W = P.w[m];
    __nv_bfloat16* dst = g_WP + m*WMAT_BF + ks*WSLICE_BF;
    for (int e = threadIdx.x; e < 16*FD; e += blockDim.x){
        int kr = e >> 7, c = e & 127;
        float w = W[(ks*16 + kr)*FD + c];
        __nv_bfloat16 h = __float2bfloat16_rn(w);
        __nv_bfloat16 l = __float2bfloat16_rn(w - __bfloat162float(h));
        dst[kr*LDB + c]        = h;
        dst[2176 + kr*LDB + c] = l;
    }
}

// ---------------- init ----------------
__global__ void init_kernel(const float* __restrict__ atom, const float* __restrict__ force,
                            const float* __restrict__ disp, float* __restrict__ out){
    int i = blockIdx.x*blockDim.x + threadIdx.x;
    if (i < N3F/4) {
        ((float4*)(out + NF))[i]        = ((const float4*)force)[i];
        ((float4*)(out + NF + N3F))[i]  = ((const float4*)disp)[i];
        ((float4*)g_AGG1)[i]            = make_float4(0.f,0.f,0.f,0.f);
    }
    if (i < NF/4) ((float4*)g_ATOM)[i] = ((const float4*)atom)[i];
}

// ---------------- bf16x3 wmma fused 2-layer MLP, weight-streaming ----------------
// 128 threads, 64-row tiles, warp block 32x64, 3 CTAs/SM.
// EPI 0: Y with biases   EPI 3: Y no-bias
// EPI 2: red(accout[src,d,:], m * disp_node[dst,d,:])
// EPI 4: eq1 with fused edge message: prologue computes
//        e = dist@empW + b; msg = e*h[src]*h[dst]; writes msg to Y (=g_MSG),
//        red4s msg into g_ATOM, splits msg into A tiles. `dispn` carries dist.
template<int EPI>
__global__ void __launch_bounds__(128,3)
mlp2_ws(const float* __restrict__ X, int nrows,
        const __nv_bfloat16* __restrict__ w1, const __nv_bfloat16* __restrict__ w2,
        const float* __restrict__ b1, const float* __restrict__ b2,
        float* __restrict__ Y,
        const int* __restrict__ eidx, const float* __restrict__ dispe,
        const float* __restrict__ dispn, float* __restrict__ accout,
        const float* __restrict__ empW, const float* __restrict__ empb)
{
    extern __shared__ char sb[];
    float* sB1 = (float*)(sb + OFF_B1);
    float* sB2 = (float*)(sb + OFF_B2);

    const int tid  = threadIdx.x;
    const int wid  = tid >> 5;       // 4 warps
    const int lane = tid & 31;

    sB1[tid] = b1 ? b1[tid] : 0.f;
    sB2[tid] = b2 ? b2[tid] : 0.f;

    if (EPI == 4){
        float* sEW = (float*)(sb + OFF_EW);
        float* sEB = (float*)(sb + OFF_EB);
        for (int i = tid; i < NBD*FD; i += 128) sEW[i] = empW[i];
        if (tid < FD) sEB[tid] = empb[tid];
    }
    __syncthreads();

    const __nv_bfloat16* pAH = (const __nv_bfloat16*)(sb + OFF_AH);
    const __nv_bfloat16* pAL = (const __nv_bfloat16*)(sb + OFF_AL);
    float* scr = (float*)(sb + OFF_SCR) + wid*16*SCRLD;
    const uint32_t wb0 = (uint32_t)__cvta_generic_to_shared(sb + OFF_WB);

    const int ntiles = (nrows + TROWS - 1) / TROWS;
    const int pr = wid >> 1;            // pair (row group) 0..1
    const int sub = wid & 1;            // column half
    const int wr = pr * 32;
    const int wc = sub * 64;
    const int lr = lane >> 1;           // 0..15
    const int lc = (lane & 1) * 8;      // 0 or 8

    auto copy_slice = [&](int buf, const __nv_bfloat16* src){
        uint32_t dst = wb0 + buf*8704;
        const char* s = (const char*)src;
        #pragma unroll
        for (int j = 0; j < 5; j++){
            int idx = tid + j*128;
            if (idx < 544) cpasync16(dst + idx*16, s + idx*16);
        }
    };

    for (int tile = blockIdx.x; tile < ntiles; tile += gridDim.x){
        const int row0 = tile * TROWS;

        if (EPI == 4){
            // ---- compute 16 edge messages per warp (chunked weights in regs) ----
            const float* sEW = (const float*)(sb + OFF_EW);
            const float* sEB = (const float*)(sb + OFF_EB);
            const float4 bias = ld4(sEB + lane*4);
            #pragma unroll
            for (int half = 0; half < 2; half++){
                const int rbase = wid*16 + half*8;
                float4 acc[8];
                #pragma unroll
                for (int r = 0; r < 8; r++) acc[r] = bias;
                // 5 chunks of 4 radial bases; weights cached in registers per chunk
                #pragma unroll
                for (int cb = 0; cb < 5; cb++){
                    float4 w0 = ld4(sEW + (cb*4+0)*FD + lane*4);
                    float4 w1v = ld4(sEW + (cb*4+1)*FD + lane*4);
                    float4 w2v = ld4(sEW + (cb*4+2)*FD + lane*4);
                    float4 w3 = ld4(sEW + (cb*4+3)*FD + lane*4);
                    #pragma unroll
                    for (int r = 0; r < 8; r++){
                        int e = row0 + rbase + r;
                        if (e < nrows){
                            float4 d = ld4(dispn + (size_t)e*NBD + cb*4);  // dispn = dist
                            acc[r].x = fmaf(d.x, w0.x, acc[r].x);
                            acc[r].y = fmaf(d.x, w0.y, acc[r].y);
                            acc[r].z = fmaf(d.x, w0.z, acc[r].z);
                            acc[r].w = fmaf(d.x, w0.w, acc[r].w);
                            acc[r].x = fmaf(d.y, w1v.x, acc[r].x);
                            acc[r].y = fmaf(d.y, w1v.y, acc[r].y);
                            acc[r].z = fmaf(d.y, w1v.z, acc[r].z);
                            acc[r].w = fmaf(d.y, w1v.w, acc[r].w);
                            acc[r].x = fmaf(d.z, w2v.x, acc[r].x);
                            acc[r].y = fmaf(d.z, w2v.y, acc[r].y);
                            acc[r].z = fmaf(d.z, w2v.z, acc[r].z);
                            acc[r].w = fmaf(d.z, w2v.w, acc[r].w);
                            acc[r].x = fmaf(d.w, w3.x, acc[r].x);
                            acc[r].y = fmaf(d.w, w3.y, acc[r].y);
                            acc[r].z = fmaf(d.w, w3.z, acc[r].z);
                            acc[r].w = fmaf(d.w, w3.w, acc[r].w);
                        }
                    }
                }
                #pragma unroll
                for (int r = 0; r < 8; r++){
                    int rl = rbase + r;
                    int e  = row0 + rl;
                    float4 m = make_float4(0.f,0.f,0.f,0.f);
                    if (e < nrows){
                        int s = __ldg(eidx + e);
                        int t = __ldg(eidx + NE + e);
                        float4 hs = ld4(g_H + (size_t)s*FD + lane*4);
                        float4 ht = ld4(g_H + (size_t)t*FD + lane*4);
                        m = make_float4(acc[r].x*hs.x*ht.x, acc[r].y*hs.y*ht.y,
                                        acc[r].z*hs.z*ht.z, acc[r].w*hs.w*ht.w);
                        st4(Y + (size_t)e*FD + lane*4, m);              // Y = g_MSG
                        red4(g_ATOM + (size_t)s*FD + lane*4, m);
                    }
                    split_store4(sb, OFF_AH, OFF_AL, rl, lane*4, m);
                }
            }
        } else {
            #pragma unroll 4
            for (int rr = 0; rr < 16; rr++){
                int rl  = wid*16 + rr;
                int row = row0 + rl;
                float4 v = make_float4(0.f,0.f,0.f,0.f);
                if (row < nrows) v = ld4(X + (size_t)row*FD + lane*4);
                split_store4(sb, OFF_AH, OFF_AL, rl, lane*4, v);
            }
        }

        copy_slice(0, w1); cpcommit();

        wmma::fragment<wmma::accumulator,16,16,16,float> acc[2][4];
        #pragma unroll
        for (int p = 0; p < 2; p++)
            #pragma unroll
            for (int ct = 0; ct < 4; ct++) wmma::fill_fragment(acc[p][ct], 0.f);

        // ================= stage 1: D = X @ W1 (bf16x3) =================
        #pragma unroll
        for (int ks = 0; ks < 8; ks++){
            if (ks < 7) copy_slice((ks+1)&1, w1 + (ks+1)*WSLICE_BF);
            else        copy_slice(0,        w2);
            cpcommit();
            cpwait<1>();
            __syncthreads();
            {
                const __nv_bfloat16* bufH = (const __nv_bfloat16*)(sb + OFF_WB + (ks&1)*8704);
                const __nv_bfloat16* bufL = bufH + 2176;
                wmma::fragment<wmma::matrix_a,16,16,16,__nv_bfloat16,wmma::row_major> aH[2], aL[2];
                #pragma unroll
                for (int p = 0; p < 2; p++){
                    wmma::load_matrix_sync(aH[p], pAH + (wr + p*16)*LDB + ks*16, LDB);
                    wmma::load_matrix_sync(aL[p], pAL + (wr + p*16)*LDB + ks*16, LDB);
                }
                #pragma unroll
                for (int ct = 0; ct < 4; ct++){
                    wmma::fragment<wmma::matrix_b,16,16,16,__nv_bfloat16,wmma::row_major> bH, bL;
                    wmma::load_matrix_sync(bH, bufH + wc + ct*16, LDB);
                    wmma::load_matrix_sync(bL, bufL + wc + ct*16, LDB);
                    #pragma unroll
                    for (int p = 0; p < 2; p++){
                        wmma::mma_sync(acc[p][ct], aH[p], bL, acc[p][ct]);
                        wmma::mma_sync(acc[p][ct], aL[p], bH, acc[p][ct]);
                        wmma::mma_sync(acc[p][ct], aH[p], bH, acc[p][ct]);
                    }
                }
            }
            __syncthreads();
        }

        // ---- silu(d + b1), re-split into A tiles ----
        #pragma unroll
        for (int p = 0; p < 2; p++){
            #pragma unroll
            for (int ct = 0; ct < 4; ct++){
                wmma::store_matrix_sync(scr, acc[p][ct], SCRLD, wmma::mem_row_major);
                __syncwarp();
                int c0 = wc + ct*16 + lc;
                float4 v0 = ld4(scr + lr*SCRLD + lc);
                float4 v1 = ld4(scr + lr*SCRLD + lc + 4);
                float4 bb0 = ld4(sB1 + c0);
                float4 bb1 = ld4(sB1 + c0 + 4);
                v0.x = silu_f(v0.x + bb0.x); v0.y = silu_f(v0.y + bb0.y);
                v0.z = silu_f(v0.z + bb0.z); v0.w = silu_f(v0.w + bb0.w);
                v1.x = silu_f(v1.x + bb1.x); v1.y = silu_f(v1.y + bb1.y);
                v1.z = silu_f(v1.z + bb1.z); v1.w = silu_f(v1.w + bb1.w);
                split_store4(sb, OFF_AH, OFF_AL, wr + p*16 + lr, c0,     v0);
                split_store4(sb, OFF_AH, OFF_AL, wr + p*16 + lr, c0 + 4, v1);
                __syncwarp();
            }
        }

        #pragma unroll
        for (int p = 0; p < 2; p++)
            #pragma unroll
            for (int ct = 0; ct < 4; ct++) wmma::fill_fragment(acc[p][ct], 0.f);

        // ================= stage 2: D = H @ W2 (bf16x3) =================
        #pragma unroll
        for (int ks = 0; ks < 8; ks++){
            if (ks < 7){ copy_slice((ks+1)&1, w2 + (ks+1)*WSLICE_BF); cpcommit(); cpwait<1>(); }
            else       { cpwait<0>(); }
            __syncthreads();
            {
                const __nv_bfloat16* bufH = (const __nv_bfloat16*)(sb + OFF_WB + (ks&1)*8704);
                const __nv_bfloat16* bufL = bufH + 2176;
                wmma::fragment<wmma::matrix_a,16,16,16,__nv_bfloat16,wmma::row_major> aH[2], aL[2];
                #pragma unroll
                for (int p = 0; p < 2; p++){
                    wmma::load_matrix_sync(aH[p], pAH + (wr + p*16)*LDB + ks*16, LDB);
                    wmma::load_matrix_sync(aL[p], pAL + (wr + p*16)*LDB + ks*16, LDB);
                }
                #pragma unroll
                for (int ct = 0; ct < 4; ct++){
                    wmma::fragment<wmma::matrix_b,16,16,16,__nv_bfloat16,wmma::row_major> bH, bL;
                    wmma::load_matrix_sync(bH, bufH + wc + ct*16, LDB);
                    wmma::load_matrix_sync(bL, bufL + wc + ct*16, LDB);
                    #pragma unroll
                    for (int p = 0; p < 2; p++){
                        wmma::mma_sync(acc[p][ct], aH[p], bL, acc[p][ct]);
                        wmma::mma_sync(acc[p][ct], aL[p], bH, acc[p][ct]);
                        wmma::mma_sync(acc[p][ct], aH[p], bH, acc[p][ct]);
                    }
                }
            }
            __syncthreads();
        }

        // ================= epilogue =================
        #pragma unroll
        for (int p = 0; p < 2; p++){
            const int row = row0 + wr + p*16 + lr;
            const bool valid = (row < nrows);
            int s = 0, t = 0;
            float d0 = 0.f, d1 = 0.f, d2 = 0.f;
            if (EPI == 4 && valid){
                s = __ldg(eidx + row);
                d0 = __ldg(dispe + (size_t)row*3 + 0);
                d1 = __ldg(dispe + (size_t)row*3 + 1);
                d2 = __ldg(dispe + (size_t)row*3 + 2);
            }
            if (EPI == 2 && valid){
                s = __ldg(eidx + row);
                t = __ldg(eidx + NE + row);
            }
            #pragma unroll
            for (int ct = 0; ct < 4; ct++){
                wmma::store_matrix_sync(scr, acc[p][ct], SCRLD, wmma::mem_row_major);
                __syncwarp();
                if (valid){
                    int c0 = wc + ct*16 + lc;
                    float4 m0 = ld4(scr + lr*SCRLD + lc);
                    float4 m1 = ld4(scr + lr*SCRLD + lc + 4);
                    float4 bb0 = ld4(sB2 + c0);
                    float4 bb1 = ld4(sB2 + c0 + 4);
                    m0.x += bb0.x; m0.y += bb0.y; m0.z += bb0.z; m0.w += bb0.w;
                    m1.x += bb1.x; m1.y += bb1.y; m1.z += bb1.z; m1.w += bb1.w;

                    if (EPI == 0 || EPI == 3){
                        st4(Y + (size_t)row*FD + c0,     m0);
                        st4(Y + (size_t)row*FD + c0 + 4, m1);
                    } else if (EPI == 4){
                        float* bp = accout + (size_t)s*3*FD + c0;
                        red4(bp,            make_float4(m0.x*d0, m0.y*d0, m0.z*d0, m0.w*d0));
                        red4(bp + 4,        make_float4(m1.x*d0, m1.y*d0, m1.z*d0, m1.w*d0));
                        red4(bp + FD,       make_float4(m0.x*d1, m0.y*d1, m0.z*d1, m0.w*d1));
                        red4(bp + FD + 4,   make_float4(m1.x*d1, m1.y*d1, m1.z*d1, m1.w*d1));
                        red4(bp + 2*FD,     make_float4(m0.x*d2, m0.y*d2, m0.z*d2, m0.w*d2));
                        red4(bp + 2*FD + 4, make_float4(m1.x*d2, m1.y*d2, m1.z*d2, m1.w*d2));
                    } else { // EPI == 2
                        const float* gp = dispn + (size_t)t*3*FD + c0;
                        float* bp = accout + (size_t)s*3*FD + c0;
                        #pragma unroll
                        for (int d = 0; d < 3; d++){
                            float4 g0 = ld4(gp + d*FD);
                            float4 g1 = ld4(gp + d*FD + 4);
                            red4(bp + d*FD,     make_float4(m0.x*g0.x, m0.y*g0.y, m0.z*g0.z, m0.w*g0.w));
                            red4(bp + d*FD + 4, make_float4(m1.x*g1.x, m1.y*g1.y, m1.z*g1.z, m1.w*g1.w));
                        }
                    }
                }
                __syncwarp();
            }
        }
        __syncthreads();
    }
}

// ---------------- force_out += agg1 ----------------
__global__ void force_add_kernel(float* __restrict__ outF){
    int i = blockIdx.x*blockDim.x + threadIdx.x;
    if (i < N3F/4){
        float4 a = ((float4*)g_AGG1)[i];
        float4 f = ((float4*)outF)[i];
        ((float4*)outF)[i] = make_float4(f.x+a.x, f.y+a.y, f.z+a.z, f.w+a.w);
    }
}

// ---------------- eq3: disp[src] += eq3_inv[dst] * agg1[dst] ----------------
__global__ void eq3_edge_kernel(const int* __restrict__ eidx, float* __restrict__ out_disp){
    const int tid  = threadIdx.x;
    const int lane = tid & 31;
    const int warp = (blockIdx.x*blockDim.x + tid) >> 5;
    const int nw   = (gridDim.x*blockDim.x) >> 5;
    for (int e = warp; e < NE; e += nw) {
        int s = __ldg(eidx + e);
        int t = __ldg(eidx + NE + e);
        float4 g = ld4(g_EQ3 + (size_t)t*FD + lane*4);
        #pragma unroll
        for (int d = 0; d < 3; d++) {
            float4 a = ld4(g_AGG1 + ((size_t)t*3 + d)*FD + lane*4);
            red4(out_disp + ((size_t)s*3 + d)*FD + lane*4,
                 make_float4(g.x*a.x, g.y*a.y, g.z*a.z, g.w*a.w));
        }
    }
}

// ---------------- final: inv_update + layernorm ----------------
__global__ void final_kernel(const float* __restrict__ outF, const float* __restrict__ outD,
                             const float* __restrict__ lng, const float* __restrict__ lnb,
                             float* __restrict__ outA){
    const int i = blockIdx.x;
    const int j = threadIdx.x;   // 128
    float c = 0.f;
    #pragma unroll
    for (int d = 0; d < 3; d++)
        c -= outF[((size_t)i*3 + d)*FD + j] * outD[((size_t)i*3 + d)*FD + j];
    float t = g_ATOM[(size_t)i*FD + j] + g_U[(size_t)i*FD + j] * c;

    __shared__ float red[4];
    float s = t;
    #pragma unroll
    for (int o = 16; o; o >>= 1) s += __shfl_xor_sync(0xffffffffu, s, o);
    if ((j & 31) == 0) red[j >> 5] = s;
    __syncthreads();
    float mu = (red[0]+red[1]+red[2]+red[3]) * (1.f/FD);
    __syncthreads();
    float dv = t - mu;
    float v = dv*dv;
    #pragma unroll
    for (int o = 16; o; o >>= 1) v += __shfl_xor_sync(0xffffffffu, v, o);
    if ((j & 31) == 0) red[j >> 5] = v;
    __syncthreads();
    float var = (red[0]+red[1]+red[2]+red[3]) * (1.f/FD);
    outA[(size_t)i*FD + j] = dv * rsqrtf(var + 1e-5f) * lng[j] + lnb[j];
}

// ---------------- launch ----------------
extern "C" void kernel_launch(void* const* d_in, const int* in_sizes, int n_in,
                              void* d_out, int out_size){
    const float* atom  = (const float*)d_in[0];
    const float* force = (const float*)d_in[1];
    const float* disp  = (const float*)d_in[2];
    const float* dispe = (const float*)d_in[3];
    const float* dist  = (const float*)d_in[4];
    const int*   eidx  = (const int*)  d_in[5];
    const float* nW1 = (const float*)d_in[6],  *nb1 = (const float*)d_in[7];
    const float* nW2 = (const float*)d_in[8],  *nb2 = (const float*)d_in[9];
    const float* eW  = (const float*)d_in[10], *eb  = (const float*)d_in[11];
    const float* q1W1= (const float*)d_in[12], *q1b1= (const float*)d_in[13];
    const float* q1W2= (const float*)d_in[14], *q1b2= (const float*)d_in[15];
    const float* q2W1= (const float*)d_in[16], *q2b1= (const float*)d_in[17];
    const float* q2W2= (const float*)d_in[18], *q2b2= (const float*)d_in[19];
    const float* q3W1= (const float*)d_in[20], *q3W2= (const float*)d_in[21];
    const float* uW1 = (const float*)d_in[22], *ub1 = (const float*)d_in[23];
    const float* uW2 = (const float*)d_in[24], *ub2 = (const float*)d_in[25];
    const float* lng = (const float*)d_in[26], *lnb = (const float*)d_in[27];

    float* out  = (float*)d_out;
    float* outA = out;
    float* outF = out + NF;
    float* outD = out + NF + N3F;

    float *pH, *pMSG, *pAGG, *pATOM, *pEQ3, *pU;
    cudaGetSymbolAddress((void**)&pH,    g_H);
    cudaGetSymbolAddress((void**)&pMSG,  g_MSG);
    cudaGetSymbolAddress((void**)&pAGG,  g_AGG1);
    cudaGetSymbolAddress((void**)&pATOM, g_ATOM);
    cudaGetSymbolAddress((void**)&pEQ3,  g_EQ3);
    cudaGetSymbolAddress((void**)&pU,    g_U);
    __nv_bfloat16* pWP;
    cudaGetSymbolAddress((void**)&pWP, g_WP);

    cudaFuncSetAttribute(mlp2_ws<0>, cudaFuncAttributeMaxDynamicSharedMemorySize, SMEM_TOT);
    cudaFuncSetAttribute(mlp2_ws<2>, cudaFuncAttributeMaxDynamicSharedMemorySize, SMEM_TOT);
    cudaFuncSetAttribute(mlp2_ws<3>, cudaFuncAttributeMaxDynamicSharedMemorySize, SMEM_TOT);
    cudaFuncSetAttribute(mlp2_ws<4>, cudaFuncAttributeMaxDynamicSharedMemorySize, SMEM_T4);

    const int NODE_GRID = (NN + TROWS - 1) / TROWS;   // 157
    const int EDGE_GRID = 444;                         // 3 CTAs/SM

    WPtrs P;
    P.w[0]=nW1; P.w[1]=nW2; P.w[2]=q1W1; P.w[3]=q1W2; P.w[4]=q2W1;
    P.w[5]=q2W2; P.w[6]=q3W1; P.w[7]=q3W2; P.w[8]=uW1; P.w[9]=uW2;

    // side stream + fork/join events (created once; host-side resources only)
    static cudaStream_t sB = nullptr;
    static cudaEvent_t evF0, evJ0, evF1, evJ1;
    if (sB == nullptr){
        cudaStreamCreateWithFlags(&sB, cudaStreamNonBlocking);
        cudaEventCreateWithFlags(&evF0, cudaEventDisableTiming);
        cudaEventCreateWithFlags(&evJ0, cudaEventDisableTiming);
        cudaEventCreateWithFlags(&evF1, cudaEventDisableTiming);
        cudaEventCreateWithFlags(&evJ1, cudaEventDisableTiming);
    }

    // ---- fork 0: init (side) || prep_w + h-MLP (main) ----
    cudaEventRecord(evF0, 0);
    cudaStreamWaitEvent(sB, evF0, 0);
    init_kernel<<<N3F/4/256, 256, 0, sB>>>(atom, force, disp, out);

    prep_w<<<80, 256>>>(P);
    mlp2_ws<0><<<NODE_GRID, 128, SMEM_TOT>>>(atom, NN, pWP + 0*WMAT_BF, pWP + 1*WMAT_BF,
                                             nb1, nb2, pH, nullptr, nullptr, nullptr, nullptr,
                                             nullptr, nullptr);
    cudaEventRecord(evJ0, sB);
    cudaStreamWaitEvent(0, evJ0, 0);

    // ---- fused eq1: edge message (msg -> g_MSG, red4 -> g_ATOM) + eq1 scatter -> agg1 ----
    mlp2_ws<4><<<EDGE_GRID, 128, SMEM_T4>>>(nullptr, NE, pWP + 2*WMAT_BF, pWP + 3*WMAT_BF,
                                            q1b1, q1b2, pMSG, eidx, dispe, dist, pAGG,
                                            eW, eb);

    // ---- fork 1: eq2 (side) || force_add + eq3-chain + upd-MLP (main) ----
    cudaEventRecord(evF1, 0);
    cudaStreamWaitEvent(sB, evF1, 0);
    mlp2_ws<2><<<EDGE_GRID, 128, SMEM_TOT, sB>>>(pMSG, NE, pWP + 4*WMAT_BF, pWP + 5*WMAT_BF,
                                                 q2b1, q2b2, nullptr, eidx, nullptr, disp, outD,
                                                 nullptr, nullptr);

    force_add_kernel<<<(N3F/4 + 255)/256, 256>>>(outF);
    mlp2_ws<3><<<NODE_GRID, 128, SMEM_TOT>>>(pATOM, NN, pWP + 6*WMAT_BF, pWP + 7*WMAT_BF,
                                             nullptr, nullptr, pEQ3, nullptr, nullptr, nullptr, nullptr,
                                             nullptr, nullptr);
    eq3_edge_kernel<<<800, 256>>>(eidx, outD);
    mlp2_ws<0><<<NODE_GRID, 128, SMEM_TOT>>>(pATOM, NN, pWP + 8*WMAT_BF, pWP + 9*WMAT_BF,
                                             ub1, ub2, pU, nullptr, nullptr, nullptr, nullptr,
                                             nullptr, nullptr);
    cudaEventRecord(evJ1, sB);
    cudaStreamWaitEvent(0, evJ1, 0);

    // ---- join: inv_update coupling + layernorm ----
    final_kernel<<<NN, 128>>>(outF, outD, lng, lnb, outA);
}

// round 15
// speedup vs baseline: 1.1026x; 1.0216x over previous
#include <cuda_runtime.h>
#include <cuda_bf16.h>
#include <math.h>
#include <stdint.h>
#include <mma.h>

using namespace nvcuda;

#define NN 10000
#define NE 200000
#define FD 128
#define NBD 20
#define NF (NN*FD)
#define N3F (NN*3*FD)
#define LDB 136          // bf16 tile leading dim
#define SCRLD 20         // fp32 scratch leading dim
#define TROWS 64         // rows per CTA tile

// byte offsets inside dynamic SMEM (per 128-thread CTA)
#define OFF_AH   0                 // 64 x 136 bf16 = 17408
#define OFF_AL   17408
#define OFF_WB   34816             // 2 weight-slice buffers x 8704 B
#define OFF_SCR  52224             // 4 warps x 16*20*4 = 5120
#define OFF_B1   57344
#define OFF_B2   57856
#define SMEM_TOT 58368
// EPI4 (fused edge-message) extras
#define OFF_EW   58368             // empW 20x128 fp32 = 10240
#define OFF_EB   68608             // empb 512
#define SMEM_T4  69120

#define WSLICE_BF 4352             // bf16 per k-slice block (H 16x136 + L 16x136)
#define WMAT_BF  (8*WSLICE_BF)     // bf16 per prepared matrix

// ---------------- scratch (device globals; no allocation) ----------------
__device__ float g_H[NF];
__device__ __nv_bfloat16 g_MSGH[NE*FD];      // msg hi (bf16)
__device__ __nv_bfloat16 g_MSGL[NE*FD];      // msg lo (bf16)
__device__ float g_AGG1[N3F];
__device__ float g_ATOM[NF];
__device__ float g_EQ3[NF];
__device__ float g_U[NF];
__device__ __nv_bfloat16 g_WP[10*WMAT_BF];   // pre-split weights (hi/lo k-slices)

// ---------------- helpers ----------------
__device__ __forceinline__ float4 ld4(const float* p){ return *reinterpret_cast<const float4*>(p); }
__device__ __forceinline__ void st4(float* p, float4 v){ *reinterpret_cast<float4*>(p) = v; }
__device__ __forceinline__ float silu_f(float x){ return x * (1.0f/(1.0f + __expf(-x))); }
__device__ __forceinline__ void red4(float* p, float4 v){
    asm volatile("red.global.add.v4.f32 [%0], {%1,%2,%3,%4};"
        :: "l"(p), "f"(v.x), "f"(v.y), "f"(v.z), "f"(v.w) : "memory");
}
__device__ __forceinline__ uint32_t packbf2(float a, float b){
    __nv_bfloat162 t = __floats2bfloat162_rn(a, b);
    return *reinterpret_cast<uint32_t*>(&t);
}
__device__ __forceinline__ float bf2f(uint32_t u, int half){
    __nv_bfloat162 t = *reinterpret_cast<__nv_bfloat162*>(&u);
    return half ? __bfloat162float(__high2bfloat16(t)) : __bfloat162float(__low2bfloat16(t));
}
__device__ __forceinline__ void cpasync16(uint32_t saddr, const void* gaddr){
    asm volatile("cp.async.cg.shared.global [%0], [%1], 16;" :: "r"(saddr), "l"(gaddr) : "memory");
}
__device__ __forceinline__ void cpcommit(){
    asm volatile("cp.async.commit_group;" ::: "memory");
}
template<int N> __device__ __forceinline__ void cpwait(){
    asm volatile("cp.async.wait_group %0;" :: "n"(N) : "memory");
}

// split x into hi(bf16) + lo(bf16 of residual); write 4 cols to smem tiles;
// optionally also write the packed hi/lo words to global (gh/gl at this row+col).
__device__ __forceinline__ void split_store4(char* sb, int offH, int offL,
                                             int row, int col, float4 v,
                                             __nv_bfloat16* gh = nullptr,
                                             __nv_bfloat16* gl = nullptr){
    uint32_t h0 = packbf2(v.x, v.y);
    uint32_t h1 = packbf2(v.z, v.w);
    float4 r;
    r.x = v.x - bf2f(h0,0); r.y = v.y - bf2f(h0,1);
    r.z = v.z - bf2f(h1,0); r.w = v.w - bf2f(h1,1);
    uint32_t l0 = packbf2(r.x, r.y);
    uint32_t l1 = packbf2(r.z, r.w);
    uint2 hh; hh.x = h0; hh.y = h1;
    uint2 ll; ll.x = l0; ll.y = l1;
    *reinterpret_cast<uint2*>(sb + offH + (row*LDB + col)*2) = hh;
    *reinterpret_cast<uint2*>(sb + offL + (row*LDB + col)*2) = ll;
    if (gh){
        *reinterpret_cast<uint2*>(gh) = hh;
        *reinterpret_cast<uint2*>(gl) = ll;
    }
}

// ---------------- weight prep: fp32 [k][c] -> bf16 hi/lo k-slice blocks ----------------
struct WPtrs { const float* w[10]; };

__global__ void prep_w(WPtrs P){
    int m  = blockIdx.x >> 3;
    int ks = blockIdx.x & 7;
    const float* W = P.w[m];
    __nv_bfloat16* dst = g_WP + m*WMAT_BF + ks*WSLICE_BF;
    for (int e = threadIdx.x; e < 16*FD; e += blockDim.x){
        int kr = e >> 7, c = e & 127;
        float w = W[(ks*16 + kr)*FD + c];
        __nv_bfloat16 h = __float2bfloat16_rn(w);
        __nv_bfloat16 l = __float2bfloat16_rn(w - __bfloat162float(h));
        dst[kr*LDB + c]        = h;
        dst[2176 + kr*LDB + c] = l;
    }
}

// ---------------- init ----------------
__global__ void init_kernel(const float* __restrict__ atom, const float* __restrict__ force,
                            const float* __restrict__ disp, float* __restrict__ out){
    int i = blockIdx.x*blockDim.x + threadIdx.x;
    if (i < N3F/4) {
        ((float4*)(out + NF))[i]        = ((const float4*)force)[i];
        ((float4*)(out + NF + N3F))[i]  = ((const float4*)disp)[i];
        ((float4*)g_AGG1)[i]            = make_float4(0.f,0.f,0.f,0.f);
    }
    if (i < NF/4) ((float4*)g_ATOM)[i] = ((const float4*)atom)[i];
}

// ---------------- bf16x3 wmma fused 2-layer MLP, weight-streaming ----------------
// 128 threads, 64-row tiles, warp block 32x64, 3 CTAs/SM.
// EPI 0: Y with biases   EPI 3: Y no-bias
// EPI 2: eq2 — prologue cp.asyncs pre-split msg (g_MSGH/g_MSGL) into A tiles;
//        epilogue red(accout[src,d,:], m * disp_node[dst,d,:])
// EPI 4: eq1 with fused edge message: prologue computes
//        e = dist@empW + b; msg = e*h[src]*h[dst]; stores split msg to
//        g_MSGH/g_MSGL, red4s msg into g_ATOM, splits into A tiles.
//        `dispn` carries dist.
template<int EPI>
__global__ void __launch_bounds__(128,3)
mlp2_ws(const float* __restrict__ X, int nrows,
        const __nv_bfloat16* __restrict__ w1, const __nv_bfloat16* __restrict__ w2,
        const float* __restrict__ b1, const float* __restrict__ b2,
        float* __restrict__ Y,
        const int* __restrict__ eidx, const float* __restrict__ dispe,
        const float* __restrict__ dispn, float* __restrict__ accout,
        const float* __restrict__ empW, const float* __restrict__ empb)
{
    extern __shared__ char sb[];
    float* sB1 = (float*)(sb + OFF_B1);
    float* sB2 = (float*)(sb + OFF_B2);

    const int tid  = threadIdx.x;
    const int wid  = tid >> 5;       // 4 warps
    const int lane = tid & 31;

    sB1[tid] = b1 ? b1[tid] : 0.f;
    sB2[tid] = b2 ? b2[tid] : 0.f;

    if (EPI == 4){
        float* sEW = (float*)(sb + OFF_EW);
        float* sEB = (float*)(sb + OFF_EB);
        for (int i = tid; i < NBD*FD; i += 128) sEW[i] = empW[i];
        if (tid < FD) sEB[tid] = empb[tid];
    }
    __syncthreads();

    const __nv_bfloat16* pAH = (const __nv_bfloat16*)(sb + OFF_AH);
    const __nv_bfloat16* pAL = (const __nv_bfloat16*)(sb + OFF_AL);
    float* scr = (float*)(sb + OFF_SCR) + wid*16*SCRLD;
    const uint32_t wb0 = (uint32_t)__cvta_generic_to_shared(sb + OFF_WB);
    const uint32_t uA0 = (uint32_t)__cvta_generic_to_shared(sb);

    const int ntiles = (nrows + TROWS - 1) / TROWS;
    const int pr = wid >> 1;            // pair (row group) 0..1
    const int sub = wid & 1;            // column half
    const int wr = pr * 32;
    const int wc = sub * 64;
    const int lr = lane >> 1;           // 0..15
    const int lc = (lane & 1) * 8;      // 0 or 8

    auto copy_slice = [&](int buf, const __nv_bfloat16* src){
        uint32_t dst = wb0 + buf*8704;
        const char* s = (const char*)src;
        #pragma unroll
        for (int j = 0; j < 5; j++){
            int idx = tid + j*128;
            if (idx < 544) cpasync16(dst + idx*16, s + idx*16);
        }
    };

    for (int tile = blockIdx.x; tile < ntiles; tile += gridDim.x){
        const int row0 = tile * TROWS;

        if (EPI == 4){
            // ---- compute 16 edge messages per warp (chunked weights in regs) ----
            const float* sEW = (const float*)(sb + OFF_EW);
            const float* sEB = (const float*)(sb + OFF_EB);
            const float4 bias = ld4(sEB + lane*4);
            #pragma unroll
            for (int half = 0; half < 2; half++){
                const int rbase = wid*16 + half*8;
                float4 acc[8];
                #pragma unroll
                for (int r = 0; r < 8; r++) acc[r] = bias;
                #pragma unroll
                for (int cb = 0; cb < 5; cb++){
                    float4 w0 = ld4(sEW + (cb*4+0)*FD + lane*4);
                    float4 w1v = ld4(sEW + (cb*4+1)*FD + lane*4);
                    float4 w2v = ld4(sEW + (cb*4+2)*FD + lane*4);
                    float4 w3 = ld4(sEW + (cb*4+3)*FD + lane*4);
                    #pragma unroll
                    for (int r = 0; r < 8; r++){
                        int e = row0 + rbase + r;
                        if (e < nrows){
                            float4 d = ld4(dispn + (size_t)e*NBD + cb*4);  // dispn = dist
                            acc[r].x = fmaf(d.x, w0.x, acc[r].x);
                            acc[r].y = fmaf(d.x, w0.y, acc[r].y);
                            acc[r].z = fmaf(d.x, w0.z, acc[r].z);
                            acc[r].w = fmaf(d.x, w0.w, acc[r].w);
                            acc[r].x = fmaf(d.y, w1v.x, acc[r].x);
                            acc[r].y = fmaf(d.y, w1v.y, acc[r].y);
                            acc[r].z = fmaf(d.y, w1v.z, acc[r].z);
                            acc[r].w = fmaf(d.y, w1v.w, acc[r].w);
                            acc[r].x = fmaf(d.z, w2v.x, acc[r].x);
                            acc[r].y = fmaf(d.z, w2v.y, acc[r].y);
                            acc[r].z = fmaf(d.z, w2v.z, acc[r].z);
                            acc[r].w = fmaf(d.z, w2v.w, acc[r].w);
                            acc[r].x = fmaf(d.w, w3.x, acc[r].x);
                            acc[r].y = fmaf(d.w, w3.y, acc[r].y);
                            acc[r].z = fmaf(d.w, w3.z, acc[r].z);
                            acc[r].w = fmaf(d.w, w3.w, acc[r].w);
                        }
                    }
                }
                #pragma unroll
                for (int r = 0; r < 8; r++){
                    int rl = rbase + r;
                    int e  = row0 + rl;
                    float4 m = make_float4(0.f,0.f,0.f,0.f);
                    if (e < nrows){
                        int s = __ldg(eidx + e);
                        int t = __ldg(eidx + NE + e);
                        float4 hs = ld4(g_H + (size_t)s*FD + lane*4);
                        float4 ht = ld4(g_H + (size_t)t*FD + lane*4);
                        m = make_float4(acc[r].x*hs.x*ht.x, acc[r].y*hs.y*ht.y,
                                        acc[r].z*hs.z*ht.z, acc[r].w*hs.w*ht.w);
                        red4(g_ATOM + (size_t)s*FD + lane*4, m);
                        split_store4(sb, OFF_AH, OFF_AL, rl, lane*4, m,
                                     g_MSGH + (size_t)e*FD + lane*4,
                                     g_MSGL + (size_t)e*FD + lane*4);
                    } else {
                        split_store4(sb, OFF_AH, OFF_AL, rl, lane*4, m);
                    }
                }
            }
        } else if (EPI == 2){
            // ---- cp.async pre-split msg rows straight into A tiles ----
            const int chunk = lane & 15;            // 16B chunk within row
            const int hl    = lane >> 4;            // 0 = hi, 1 = lo
            const __nv_bfloat16* gsrc = hl ? g_MSGL : g_MSGH;
            const uint32_t dbase = uA0 + (hl ? OFF_AL : OFF_AH);
            #pragma unroll 4
            for (int rr = 0; rr < 16; rr++){
                int rl  = wid*16 + rr;
                int row = row0 + rl;                 // NE % 64 == 0: always valid
                cpasync16(dbase + (uint32_t)rl*272 + chunk*16,
                          (const char*)(gsrc + (size_t)row*FD) + chunk*16);
            }
            cpcommit();
        } else {
            #pragma unroll 4
            for (int rr = 0; rr < 16; rr++){
                int rl  = wid*16 + rr;
                int row = row0 + rl;
                float4 v = make_float4(0.f,0.f,0.f,0.f);
                if (row < nrows) v = ld4(X + (size_t)row*FD + lane*4);
                split_store4(sb, OFF_AH, OFF_AL, rl, lane*4, v);
            }
        }

        copy_slice(0, w1); cpcommit();

        wmma::fragment<wmma::accumulator,16,16,16,float> acc[2][4];
        #pragma unroll
        for (int p = 0; p < 2; p++)
            #pragma unroll
            for (int ct = 0; ct < 4; ct++) wmma::fill_fragment(acc[p][ct], 0.f);

        // ================= stage 1: D = X @ W1 (bf16x3) =================
        #pragma unroll
        for (int ks = 0; ks < 8; ks++){
            if (ks < 7) copy_slice((ks+1)&1, w1 + (ks+1)*WSLICE_BF);
            else        copy_slice(0,        w2);
            cpcommit();
            cpwait<1>();
            __syncthreads();
            {
                const __nv_bfloat16* bufH = (const __nv_bfloat16*)(sb + OFF_WB + (ks&1)*8704);
                const __nv_bfloat16* bufL = bufH + 2176;
                wmma::fragment<wmma::matrix_a,16,16,16,__nv_bfloat16,wmma::row_major> aH[2], aL[2];
                #pragma unroll
                for (int p = 0; p < 2; p++){
                    wmma::load_matrix_sync(aH[p], pAH + (wr + p*16)*LDB + ks*16, LDB);
                    wmma::load_matrix_sync(aL[p], pAL + (wr + p*16)*LDB + ks*16, LDB);
                }
                #pragma unroll
                for (int ct = 0; ct < 4; ct++){
                    wmma::fragment<wmma::matrix_b,16,16,16,__nv_bfloat16,wmma::row_major> bH, bL;
                    wmma::load_matrix_sync(bH, bufH + wc + ct*16, LDB);
                    wmma::load_matrix_sync(bL, bufL + wc + ct*16, LDB);
                    #pragma unroll
                    for (int p = 0; p < 2; p++){
                        wmma::mma_sync(acc[p][ct], aH[p], bL, acc[p][ct]);
                        wmma::mma_sync(acc[p][ct], aL[p], bH, acc[p][ct]);
                        wmma::mma_sync(acc[p][ct], aH[p], bH, acc[p][ct]);
                    }
                }
            }
            __syncthreads();
        }

        // ---- silu(d + b1), re-split into A tiles ----
        #pragma unroll
        for (int p = 0; p < 2; p++){
            #pragma unroll
            for (int ct = 0; ct < 4; ct++){
                wmma::store_matrix_sync(scr, acc[p][ct], SCRLD, wmma::mem_row_major);
                __syncwarp();
                int c0 = wc + ct*16 + lc;
                float4 v0 = ld4(scr + lr*SCRLD + lc);
                float4 v1 = ld4(scr + lr*SCRLD + lc + 4);
                float4 bb0 = ld4(sB1 + c0);
                float4 bb1 = ld4(sB1 + c0 + 4);
                v0.x = silu_f(v0.x + bb0.x); v0.y = silu_f(v0.y + bb0.y);
                v0.z = silu_f(v0.z + bb0.z); v0.w = silu_f(v0.w + bb0.w);
                v1.x = silu_f(v1.x + bb1.x); v1.y = silu_f(v1.y + bb1.y);
                v1.z = silu_f(v1.z + bb1.z); v1.w = silu_f(v1.w + bb1.w);
                split_store4(sb, OFF_AH, OFF_AL, wr + p*16 + lr, c0,     v0);
                split_store4(sb, OFF_AH, OFF_AL, wr + p*16 + lr, c0 + 4, v1);
                __syncwarp();
            }
        }

        #pragma unroll
        for (int p = 0; p < 2; p++)
            #pragma unroll
            for (int ct = 0; ct < 4; ct++) wmma::fill_fragment(acc[p][ct], 0.f);

        // ================= stage 2: D = H @ W2 (bf16x3) =================
        #pragma unroll
        for (int ks = 0; ks < 8; ks++){
            if (ks < 7){ copy_slice((ks+1)&1, w2 + (ks+1)*WSLICE_BF); cpcommit(); cpwait<1>(); }
            else       { cpwait<0>(); }
            __syncthreads();
            {
                const __nv_bfloat16* bufH = (const __nv_bfloat16*)(sb + OFF_WB + (ks&1)*8704);
                const __nv_bfloat16* bufL = bufH + 2176;
                wmma::fragment<wmma::matrix_a,16,16,16,__nv_bfloat16,wmma::row_major> aH[2], aL[2];
                #pragma unroll
                for (int p = 0; p < 2; p++){
                    wmma::load_matrix_sync(aH[p], pAH + (wr + p*16)*LDB + ks*16, LDB);
                    wmma::load_matrix_sync(aL[p], pAL + (wr + p*16)*LDB + ks*16, LDB);
                }
                #pragma unroll
                for (int ct = 0; ct < 4; ct++){
                    wmma::fragment<wmma::matrix_b,16,16,16,__nv_bfloat16,wmma::row_major> bH, bL;
                    wmma::load_matrix_sync(bH, bufH + wc + ct*16, LDB);
                    wmma::load_matrix_sync(bL, bufL + wc + ct*16, LDB);
                    #pragma unroll
                    for (int p = 0; p < 2; p++){
                        wmma::mma_sync(acc[p][ct], aH[p], bL, acc[p][ct]);
                        wmma::mma_sync(acc[p][ct], aL[p], bH, acc[p][ct]);
                        wmma::mma_sync(acc[p][ct], aH[p], bH, acc[p][ct]);
                    }
                }
            }
            __syncthreads();
        }

        // ================= epilogue =================
        #pragma unroll
        for (int p = 0; p < 2; p++){
            const int row = row0 + wr + p*16 + lr;
            const bool valid = (row < nrows);
            int s = 0, t = 0;
            float d0 = 0.f, d1 = 0.f, d2 = 0.f;
            if (EPI == 4 && valid){
                s = __ldg(eidx + row);
                d0 = __ldg(dispe + (size_t)row*3 + 0);
                d1 = __ldg(dispe + (size_t)row*3 + 1);
                d2 = __ldg(dispe + (size_t)row*3 + 2);
            }
            if (EPI == 2 && valid){
                s = __ldg(eidx + row);
                t = __ldg(eidx + NE + row);
            }
            #pragma unroll
            for (int ct = 0; ct < 4; ct++){
                wmma::store_matrix_sync(scr, acc[p][ct], SCRLD, wmma::mem_row_major);
                __syncwarp();
                if (valid){
                    int c0 = wc + ct*16 + lc;
                    float4 m0 = ld4(scr + lr*SCRLD + lc);
                    float4 m1 = ld4(scr + lr*SCRLD + lc + 4);
                    float4 bb0 = ld4(sB2 + c0);
                    float4 bb1 = ld4(sB2 + c0 + 4);
                    m0.x += bb0.x; m0.y += bb0.y; m0.z += bb0.z; m0.w += bb0.w;
                    m1.x += bb1.x; m1.y += bb1.y; m1.z += bb1.z; m1.w += bb1.w;

                    if (EPI == 0 || EPI == 3){
                        st4(Y + (size_t)row*FD + c0,     m0);
                        st4(Y + (size_t)row*FD + c0 + 4, m1);
                    } else if (EPI == 4){
                        float* bp = accout + (size_t)s*3*FD + c0;
                        red4(bp,            make_float4(m0.x*d0, m0.y*d0, m0.z*d0, m0.w*d0));
                        red4(bp + 4,        make_float4(m1.x*d0, m1.y*d0, m1.z*d0, m1.w*d0));
                        red4(bp + FD,       make_float4(m0.x*d1, m0.y*d1, m0.z*d1, m0.w*d1));
                        red4(bp + FD + 4,   make_float4(m1.x*d1, m1.y*d1, m1.z*d1, m1.w*d1));
                        red4(bp + 2*FD,     make_float4(m0.x*d2, m0.y*d2, m0.z*d2, m0.w*d2));
                        red4(bp + 2*FD + 4, make_float4(m1.x*d2, m1.y*d2, m1.z*d2, m1.w*d2));
                    } else { // EPI == 2
                        const float* gp = dispn + (size_t)t*3*FD + c0;
                        float* bp = accout + (size_t)s*3*FD + c0;
                        #pragma unroll
                        for (int d = 0; d < 3; d++){
                            float4 g0 = ld4(gp + d*FD);
                            float4 g1 = ld4(gp + d*FD + 4);
                            red4(bp + d*FD,     make_float4(m0.x*g0.x, m0.y*g0.y, m0.z*g0.z, m0.w*g0.w));
                            red4(bp + d*FD + 4, make_float4(m1.x*g1.x, m1.y*g1.y, m1.z*g1.z, m1.w*g1.w));
                        }
                    }
                }
                __syncwarp();
            }
        }
        __syncthreads();
    }
}

// ---------------- force_out += agg1 ----------------
__global__ void force_add_kernel(float* __restrict__ outF){
    int i = blockIdx.x*blockDim.x + threadIdx.x;
    if (i < N3F/4){
        float4 a = ((float4*)g_AGG1)[i];
        float4 f = ((float4*)outF)[i];
        ((float4*)outF)[i] = make_float4(f.x+a.x, f.y+a.y, f.z+a.z, f.w+a.w);
    }
}

// ---------------- eq3: disp[src] += eq3_inv[dst] * agg1[dst] ----------------
__global__ void eq3_edge_kernel(const int* __restrict__ eidx, float* __restrict__ out_disp){
    const int tid  = threadIdx.x;
    const int lane = tid & 31;
    const int warp = (blockIdx.x*blockDim.x + tid) >> 5;
    const int nw   = (gridDim.x*blockDim.x) >> 5;
    for (int e = warp; e < NE; e += nw) {
        int s = __ldg(eidx + e);
        int t = __ldg(eidx + NE + e);
        float4 g = ld4(g_EQ3 + (size_t)t*FD + lane*4);
        #pragma unroll
        for (int d = 0; d < 3; d++) {
            float4 a = ld4(g_AGG1 + ((size_t)t*3 + d)*FD + lane*4);
            red4(out_disp + ((size_t)s*3 + d)*FD + lane*4,
                 make_float4(g.x*a.x, g.y*a.y, g.z*a.z, g.w*a.w));
        }
    }
}

// ---------------- final: inv_update + layernorm ----------------
__global__ void final_kernel(const float* __restrict__ outF, const float* __restrict__ outD,
                             const float* __restrict__ lng, const float* __restrict__ lnb,
                             float* __restrict__ outA){
    const int i = blockIdx.x;
    const int j = threadIdx.x;   // 128
    float c = 0.f;
    #pragma unroll
    for (int d = 0; d < 3; d++)
        c -= outF[((size_t)i*3 + d)*FD + j] * outD[((size_t)i*3 + d)*FD + j];
    float t = g_ATOM[(size_t)i*FD + j] + g_U[(size_t)i*FD + j] * c;

    __shared__ float red[4];
    float s = t;
    #pragma unroll
    for (int o = 16; o; o >>= 1) s += __shfl_xor_sync(0xffffffffu, s, o);
    if ((j & 31) == 0) red[j >> 5] = s;
    __syncthreads();
    float mu = (red[0]+red[1]+red[2]+red[3]) * (1.f/FD);
    __syncthreads();
    float dv = t - mu;
    float v = dv*dv;
    #pragma unroll
    for (int o = 16; o; o >>= 1) v += __shfl_xor_sync(0xffffffffu, v, o);
    if ((j & 31) == 0) red[j >> 5] = v;
    __syncthreads();
    float var = (red[0]+red[1]+red[2]+red[3]) * (1.f/FD);
    outA[(size_t)i*FD + j] = dv * rsqrtf(var + 1e-5f) * lng[j] + lnb[j];
}

// ---------------- launch ----------------
extern "C" void kernel_launch(void* const* d_in, const int* in_sizes, int n_in,
                              void* d_out, int out_size){
    const float* atom  = (const float*)d_in[0];
    const float* force = (const float*)d_in[1];
    const float* disp  = (const float*)d_in[2];
    const float* dispe = (const float*)d_in[3];
    const float* dist  = (const float*)d_in[4];
    const int*   eidx  = (const int*)  d_in[5];
    const float* nW1 = (const float*)d_in[6],  *nb1 = (const float*)d_in[7];
    const float* nW2 = (const float*)d_in[8],  *nb2 = (const float*)d_in[9];
    const float* eW  = (const float*)d_in[10], *eb  = (const float*)d_in[11];
    const float* q1W1= (const float*)d_in[12], *q1b1= (const float*)d_in[13];
    const float* q1W2= (const float*)d_in[14], *q1b2= (const float*)d_in[15];
    const float* q2W1= (const float*)d_in[16], *q2b1= (const float*)d_in[17];
    const float* q2W2= (const float*)d_in[18], *q2b2= (const float*)d_in[19];
    const float* q3W1= (const float*)d_in[20], *q3W2= (const float*)d_in[21];
    const float* uW1 = (const float*)d_in[22], *ub1 = (const float*)d_in[23];
    const float* uW2 = (const float*)d_in[24], *ub2 = (const float*)d_in[25];
    const float* lng = (const float*)d_in[26], *lnb = (const float*)d_in[27];

    float* out  = (float*)d_out;
    float* outA = out;
    float* outF = out + NF;
    float* outD = out + NF + N3F;

    float *pH, *pAGG, *pATOM, *pEQ3, *pU;
    cudaGetSymbolAddress((void**)&pH,    g_H);
    cudaGetSymbolAddress((void**)&pAGG,  g_AGG1);
    cudaGetSymbolAddress((void**)&pATOM, g_ATOM);
    cudaGetSymbolAddress((void**)&pEQ3,  g_EQ3);
    cudaGetSymbolAddress((void**)&pU,    g_U);
    __nv_bfloat16* pWP;
    cudaGetSymbolAddress((void**)&pWP, g_WP);

    cudaFuncSetAttribute(mlp2_ws<0>, cudaFuncAttributeMaxDynamicSharedMemorySize, SMEM_TOT);
    cudaFuncSetAttribute(mlp2_ws<2>, cudaFuncAttributeMaxDynamicSharedMemorySize, SMEM_TOT);
    cudaFuncSetAttribute(mlp2_ws<3>, cudaFuncAttributeMaxDynamicSharedMemorySize, SMEM_TOT);
    cudaFuncSetAttribute(mlp2_ws<4>, cudaFuncAttributeMaxDynamicSharedMemorySize, SMEM_T4);

    const int NODE_GRID = (NN + TROWS - 1) / TROWS;   // 157
    const int EDGE_GRID = 444;                         // 3 CTAs/SM

    WPtrs P;
    P.w[0]=nW1; P.w[1]=nW2; P.w[2]=q1W1; P.w[3]=q1W2; P.w[4]=q2W1;
    P.w[5]=q2W2; P.w[6]=q3W1; P.w[7]=q3W2; P.w[8]=uW1; P.w[9]=uW2;

    // side stream + fork/join events (created once; host-side resources only)
    static cudaStream_t sB = nullptr;
    static cudaEvent_t evF0, evJ0, evF1, evJ1;
    if (sB == nullptr){
        cudaStreamCreateWithFlags(&sB, cudaStreamNonBlocking);
        cudaEventCreateWithFlags(&evF0, cudaEventDisableTiming);
        cudaEventCreateWithFlags(&evJ0, cudaEventDisableTiming);
        cudaEventCreateWithFlags(&evF1, cudaEventDisableTiming);
        cudaEventCreateWithFlags(&evJ1, cudaEventDisableTiming);
    }

    // ---- fork 0: init (side) || prep_w + h-MLP (main) ----
    cudaEventRecord(evF0, 0);
    cudaStreamWaitEvent(sB, evF0, 0);
    init_kernel<<<N3F/4/256, 256, 0, sB>>>(atom, force, disp, out);

    prep_w<<<80, 256>>>(P);
    mlp2_ws<0><<<NODE_GRID, 128, SMEM_TOT>>>(atom, NN, pWP + 0*WMAT_BF, pWP + 1*WMAT_BF,
                                             nb1, nb2, pH, nullptr, nullptr, nullptr, nullptr,
                                             nullptr, nullptr);
    cudaEventRecord(evJ0, sB);
    cudaStreamWaitEvent(0, evJ0, 0);

    // ---- fused eq1: edge message (split msg -> g_MSGH/L, red4 -> g_ATOM) + eq1 scatter ----
    mlp2_ws<4><<<EDGE_GRID, 128, SMEM_T4>>>(nullptr, NE, pWP + 2*WMAT_BF, pWP + 3*WMAT_BF,
                                            q1b1, q1b2, nullptr, eidx, dispe, dist, pAGG,
                                            eW, eb);

    // ---- fork 1: eq2 -> upd-MLP (side) || force_add -> eq3inv -> eq3 scatter (main) ----
    cudaEventRecord(evF1, 0);
    cudaStreamWaitEvent(sB, evF1, 0);
    mlp2_ws<2><<<EDGE_GRID, 128, SMEM_TOT, sB>>>(nullptr, NE, pWP + 4*WMAT_BF, pWP + 5*WMAT_BF,
                                                 q2b1, q2b2, nullptr, eidx, nullptr, disp, outD,
                                                 nullptr, nullptr);
    mlp2_ws<0><<<NODE_GRID, 128, SMEM_TOT, sB>>>(pATOM, NN, pWP + 8*WMAT_BF, pWP + 9*WMAT_BF,
                                                 ub1, ub2, pU, nullptr, nullptr, nullptr, nullptr,
                                                 nullptr, nullptr);

    force_add_kernel<<<(N3F/4 + 255)/256, 256>>>(outF);
    mlp2_ws<3><<<NODE_GRID, 128, SMEM_TOT>>>(pATOM, NN, pWP + 6*WMAT_BF, pWP + 7*WMAT_BF,
                                             nullptr, nullptr, pEQ3, nullptr, nullptr, nullptr, nullptr,
                                             nullptr, nullptr);
    eq3_edge_kernel<<<800, 256>>>(eidx, outD);
    cudaEventRecord(evJ1, sB);
    cudaStreamWaitEvent(0, evJ1, 0);

    // ---- join: inv_update coupling + layernorm ----
    final_kernel<<<NN, 128>>>(outF, outD, lng, lnb, outA);
}

// round 16
// speedup vs baseline: 1.1149x; 1.0112x over previous
#include <cuda_runtime.h>
#include <cuda_bf16.h>
#include <math.h>
#include <stdint.h>
#include <mma.h>

using namespace nvcuda;

#define NN 10000
#define NE 200000
#define FD 128
#define NBD 20
#define NF (NN*FD)
#define N3F (NN*3*FD)
#define LDB 136          // bf16 tile leading dim
#define SCRLD 20         // fp32 scratch leading dim
#define TROWS 64         // rows per CTA tile

// byte offsets inside dynamic SMEM (per 128-thread CTA)
#define OFF_AH   0                 // 64 x 136 bf16 = 17408
#define OFF_AL   17408
#define OFF_WB   34816             // 2 weight-slice buffers x 8704 B
#define OFF_SCR  52224             // 4 warps x 16*20*4 = 5120
#define OFF_B1   57344
#define OFF_B2   57856
#define SMEM_TOT 58368
// EPI4 (fused edge-message) extras
#define OFF_EW   58368             // empW 20x128 fp32 = 10240
#define OFF_EB   68608             // empb 512
#define SMEM_T4  69120

#define WSLICE_BF 4352             // bf16 per k-slice block (H 16x136 + L 16x136)
#define WMAT_BF  (8*WSLICE_BF)     // bf16 per prepared matrix

// ---------------- scratch (device globals; no allocation) ----------------
__device__ float g_H[NF];
__device__ __nv_bfloat16 g_MSGH[NE*FD];      // msg hi (bf16)
__device__ __nv_bfloat16 g_MSGL[NE*FD];      // msg lo (bf16)
__device__ float g_AGG1[N3F];                // agg1, then P = eq3inv (x) agg1
__device__ float g_ATOM[NF];
__device__ float g_EQ3[NF];
__device__ float g_U[NF];
__device__ __nv_bfloat16 g_WP[10*WMAT_BF];   // pre-split weights (hi/lo k-slices)

// ---------------- helpers ----------------
__device__ __forceinline__ float4 ld4(const float* p){ return *reinterpret_cast<const float4*>(p); }
__device__ __forceinline__ void st4(float* p, float4 v){ *reinterpret_cast<float4*>(p) = v; }
__device__ __forceinline__ float silu_f(float x){ return x * (1.0f/(1.0f + __expf(-x))); }
__device__ __forceinline__ void red4(float* p, float4 v){
    asm volatile("red.global.add.v4.f32 [%0], {%1,%2,%3,%4};"
        :: "l"(p), "f"(v.x), "f"(v.y), "f"(v.z), "f"(v.w) : "memory");
}
__device__ __forceinline__ uint32_t packbf2(float a, float b){
    __nv_bfloat162 t = __floats2bfloat162_rn(a, b);
    return *reinterpret_cast<uint32_t*>(&t);
}
__device__ __forceinline__ float bf2f(uint32_t u, int half){
    __nv_bfloat162 t = *reinterpret_cast<__nv_bfloat162*>(&u);
    return half ? __bfloat162float(__high2bfloat16(t)) : __bfloat162float(__low2bfloat16(t));
}
__device__ __forceinline__ void cpasync16(uint32_t saddr, const void* gaddr){
    asm volatile("cp.async.cg.shared.global [%0], [%1], 16;" :: "r"(saddr), "l"(gaddr) : "memory");
}
__device__ __forceinline__ void cpcommit(){
    asm volatile("cp.async.commit_group;" ::: "memory");
}
template<int N> __device__ __forceinline__ void cpwait(){
    asm volatile("cp.async.wait_group %0;" :: "n"(N) : "memory");
}

// split x into hi(bf16) + lo(bf16 of residual); write 4 cols to smem tiles;
// optionally also write the packed hi/lo words to global (gh/gl at this row+col).
__device__ __forceinline__ void split_store4(char* sb, int offH, int offL,
                                             int row, int col, float4 v,
                                             __nv_bfloat16* gh = nullptr,
                                             __nv_bfloat16* gl = nullptr){
    uint32_t h0 = packbf2(v.x, v.y);
    uint32_t h1 = packbf2(v.z, v.w);
    float4 r;
    r.x = v.x - bf2f(h0,0); r.y = v.y - bf2f(h0,1);
    r.z = v.z - bf2f(h1,0); r.w = v.w - bf2f(h1,1);
    uint32_t l0 = packbf2(r.x, r.y);
    uint32_t l1 = packbf2(r.z, r.w);
    uint2 hh; hh.x = h0; hh.y = h1;
    uint2 ll; ll.x = l0; ll.y = l1;
    *reinterpret_cast<uint2*>(sb + offH + (row*LDB + col)*2) = hh;
    *reinterpret_cast<uint2*>(sb + offL + (row*LDB + col)*2) = ll;
    if (gh){
        *reinterpret_cast<uint2*>(gh) = hh;
        *reinterpret_cast<uint2*>(gl) = ll;
    }
}

// ---------------- weight prep: fp32 [k][c] -> bf16 hi/lo k-slice blocks ----------------
struct WPtrs { const float* w[10]; };

__global__ void prep_w(WPtrs P){
    int m  = blockIdx.x >> 3;
    int ks = blockIdx.x & 7;
    const float* W = P.w[m];
    __nv_bfloat16* dst = g_WP + m*WMAT_BF + ks*WSLICE_BF;
    for (int e = threadIdx.x; e < 16*FD; e += blockDim.x){
        int kr = e >> 7, c = e & 127;
        float w = W[(ks*16 + kr)*FD + c];
        __nv_bfloat16 h = __float2bfloat16_rn(w);
        __nv_bfloat16 l = __float2bfloat16_rn(w - __bfloat162float(h));
        dst[kr*LDB + c]        = h;
        dst[2176 + kr*LDB + c] = l;
    }
}

// ---------------- init ----------------
__global__ void init_kernel(const float* __restrict__ atom, const float* __restrict__ force,
                            const float* __restrict__ disp, float* __restrict__ out){
    int i = blockIdx.x*blockDim.x + threadIdx.x;
    if (i < N3F/4) {
        ((float4*)(out + NF))[i]        = ((const float4*)force)[i];
        ((float4*)(out + NF + N3F))[i]  = ((const float4*)disp)[i];
        ((float4*)g_AGG1)[i]            = make_float4(0.f,0.f,0.f,0.f);
    }
    if (i < NF/4) ((float4*)g_ATOM)[i] = ((const float4*)atom)[i];
}

// ---------------- bf16x3 wmma fused 2-layer MLP, weight-streaming ----------------
// 128 threads, 64-row tiles, warp block 32x64, 3 CTAs/SM.
// EPI 0: Y with biases   EPI 3: Y no-bias
// EPI 2: eq2+eq3 fused — prologue cp.asyncs pre-split msg (g_MSGH/g_MSGL) into A
//        tiles; epilogue red(accout[src,d,:], m * disp_node[dst,d,:] + P[dst,d,:])
//        where P (=eq3inv (x) agg1, precomputed) arrives via the `empW` slot.
// EPI 4: eq1 with fused edge message: prologue computes
//        e = dist@empW + b; msg = e*h[src]*h[dst]; stores split msg to
//        g_MSGH/g_MSGL, red4s msg into g_ATOM, splits into A tiles.
//        `dispn` carries dist.
template<int EPI>
__global__ void __launch_bounds__(128,3)
mlp2_ws(const float* __restrict__ X, int nrows,
        const __nv_bfloat16* __restrict__ w1, const __nv_bfloat16* __restrict__ w2,
        const float* __restrict__ b1, const float* __restrict__ b2,
        float* __restrict__ Y,
        const int* __restrict__ eidx, const float* __restrict__ dispe,
        const float* __restrict__ dispn, float* __restrict__ accout,
        const float* __restrict__ empW, const float* __restrict__ empb)
{
    extern __shared__ char sb[];
    float* sB1 = (float*)(sb + OFF_B1);
    float* sB2 = (float*)(sb + OFF_B2);

    const int tid  = threadIdx.x;
    const int wid  = tid >> 5;       // 4 warps
    const int lane = tid & 31;

    sB1[tid] = b1 ? b1[tid] : 0.f;
    sB2[tid] = b2 ? b2[tid] : 0.f;

    if (EPI == 4){
        float* sEW = (float*)(sb + OFF_EW);
        float* sEB = (float*)(sb + OFF_EB);
        for (int i = tid; i < NBD*FD; i += 128) sEW[i] = empW[i];
        if (tid < FD) sEB[tid] = empb[tid];
    }
    __syncthreads();

    const __nv_bfloat16* pAH = (const __nv_bfloat16*)(sb + OFF_AH);
    const __nv_bfloat16* pAL = (const __nv_bfloat16*)(sb + OFF_AL);
    float* scr = (float*)(sb + OFF_SCR) + wid*16*SCRLD;
    const uint32_t wb0 = (uint32_t)__cvta_generic_to_shared(sb + OFF_WB);
    const uint32_t uA0 = (uint32_t)__cvta_generic_to_shared(sb);

    const int ntiles = (nrows + TROWS - 1) / TROWS;
    const int pr = wid >> 1;            // pair (row group) 0..1
    const int sub = wid & 1;            // column half
    const int wr = pr * 32;
    const int wc = sub * 64;
    const int lr = lane >> 1;           // 0..15
    const int lc = (lane & 1) * 8;      // 0 or 8

    auto copy_slice = [&](int buf, const __nv_bfloat16* src){
        uint32_t dst = wb0 + buf*8704;
        const char* s = (const char*)src;
        #pragma unroll
        for (int j = 0; j < 5; j++){
            int idx = tid + j*128;
            if (idx < 544) cpasync16(dst + idx*16, s + idx*16);
        }
    };

    for (int tile = blockIdx.x; tile < ntiles; tile += gridDim.x){
        const int row0 = tile * TROWS;

        if (EPI == 4){
            // ---- compute 16 edge messages per warp (chunked weights in regs) ----
            const float* sEW = (const float*)(sb + OFF_EW);
            const float* sEB = (const float*)(sb + OFF_EB);
            const float4 bias = ld4(sEB + lane*4);
            #pragma unroll
            for (int half = 0; half < 2; half++){
                const int rbase = wid*16 + half*8;
                float4 acc[8];
                #pragma unroll
                for (int r = 0; r < 8; r++) acc[r] = bias;
                #pragma unroll
                for (int cb = 0; cb < 5; cb++){
                    float4 w0 = ld4(sEW + (cb*4+0)*FD + lane*4);
                    float4 w1v = ld4(sEW + (cb*4+1)*FD + lane*4);
                    float4 w2v = ld4(sEW + (cb*4+2)*FD + lane*4);
                    float4 w3 = ld4(sEW + (cb*4+3)*FD + lane*4);
                    #pragma unroll
                    for (int r = 0; r < 8; r++){
                        int e = row0 + rbase + r;
                        if (e < nrows){
                            float4 d = ld4(dispn + (size_t)e*NBD + cb*4);  // dispn = dist
                            acc[r].x = fmaf(d.x, w0.x, acc[r].x);
                            acc[r].y = fmaf(d.x, w0.y, acc[r].y);
                            acc[r].z = fmaf(d.x, w0.z, acc[r].z);
                            acc[r].w = fmaf(d.x, w0.w, acc[r].w);
                            acc[r].x = fmaf(d.y, w1v.x, acc[r].x);
                            acc[r].y = fmaf(d.y, w1v.y, acc[r].y);
                            acc[r].z = fmaf(d.y, w1v.z, acc[r].z);
                            acc[r].w = fmaf(d.y, w1v.w, acc[r].w);
                            acc[r].x = fmaf(d.z, w2v.x, acc[r].x);
                            acc[r].y = fmaf(d.z, w2v.y, acc[r].y);
                            acc[r].z = fmaf(d.z, w2v.z, acc[r].z);
                            acc[r].w = fmaf(d.z, w2v.w, acc[r].w);
                            acc[r].x = fmaf(d.w, w3.x, acc[r].x);
                            acc[r].y = fmaf(d.w, w3.y, acc[r].y);
                            acc[r].z = fmaf(d.w, w3.z, acc[r].z);
                            acc[r].w = fmaf(d.w, w3.w, acc[r].w);
                        }
                    }
                }
                #pragma unroll
                for (int r = 0; r < 8; r++){
                    int rl = rbase + r;
                    int e  = row0 + rl;
                    float4 m = make_float4(0.f,0.f,0.f,0.f);
                    if (e < nrows){
                        int s = __ldg(eidx + e);
                        int t = __ldg(eidx + NE + e);
                        float4 hs = ld4(g_H + (size_t)s*FD + lane*4);
                        float4 ht = ld4(g_H + (size_t)t*FD + lane*4);
                        m = make_float4(acc[r].x*hs.x*ht.x, acc[r].y*hs.y*ht.y,
                                        acc[r].z*hs.z*ht.z, acc[r].w*hs.w*ht.w);
                        red4(g_ATOM + (size_t)s*FD + lane*4, m);
                        split_store4(sb, OFF_AH, OFF_AL, rl, lane*4, m,
                                     g_MSGH + (size_t)e*FD + lane*4,
                                     g_MSGL + (size_t)e*FD + lane*4);
                    } else {
                        split_store4(sb, OFF_AH, OFF_AL, rl, lane*4, m);
                    }
                }
            }
        } else if (EPI == 2){
            // ---- cp.async pre-split msg rows straight into A tiles ----
            const int chunk = lane & 15;            // 16B chunk within row
            const int hl    = lane >> 4;            // 0 = hi, 1 = lo
            const __nv_bfloat16* gsrc = hl ? g_MSGL : g_MSGH;
            const uint32_t dbase = uA0 + (hl ? OFF_AL : OFF_AH);
            #pragma unroll 4
            for (int rr = 0; rr < 16; rr++){
                int rl  = wid*16 + rr;
                int row = row0 + rl;                 // NE % 64 == 0: always valid
                cpasync16(dbase + (uint32_t)rl*272 + chunk*16,
                          (const char*)(gsrc + (size_t)row*FD) + chunk*16);
            }
            cpcommit();
        } else {
            #pragma unroll 4
            for (int rr = 0; rr < 16; rr++){
                int rl  = wid*16 + rr;
                int row = row0 + rl;
                float4 v = make_float4(0.f,0.f,0.f,0.f);
                if (row < nrows) v = ld4(X + (size_t)row*FD + lane*4);
                split_store4(sb, OFF_AH, OFF_AL, rl, lane*4, v);
            }
        }

        copy_slice(0, w1); cpcommit();

        wmma::fragment<wmma::accumulator,16,16,16,float> acc[2][4];
        #pragma unroll
        for (int p = 0; p < 2; p++)
            #pragma unroll
            for (int ct = 0; ct < 4; ct++) wmma::fill_fragment(acc[p][ct], 0.f);

        // ================= stage 1: D = X @ W1 (bf16x3) =================
        #pragma unroll
        for (int ks = 0; ks < 8; ks++){
            if (ks < 7) copy_slice((ks+1)&1, w1 + (ks+1)*WSLICE_BF);
            else        copy_slice(0,        w2);
            cpcommit();
            cpwait<1>();
            __syncthreads();
            {
                const __nv_bfloat16* bufH = (const __nv_bfloat16*)(sb + OFF_WB + (ks&1)*8704);
                const __nv_bfloat16* bufL = bufH + 2176;
                wmma::fragment<wmma::matrix_a,16,16,16,__nv_bfloat16,wmma::row_major> aH[2], aL[2];
                #pragma unroll
                for (int p = 0; p < 2; p++){
                    wmma::load_matrix_sync(aH[p], pAH + (wr + p*16)*LDB + ks*16, LDB);
                    wmma::load_matrix_sync(aL[p], pAL + (wr + p*16)*LDB + ks*16, LDB);
                }
                #pragma unroll
                for (int ct = 0; ct < 4; ct++){
                    wmma::fragment<wmma::matrix_b,16,16,16,__nv_bfloat16,wmma::row_major> bH, bL;
                    wmma::load_matrix_sync(bH, bufH + wc + ct*16, LDB);
                    wmma::load_matrix_sync(bL, bufL + wc + ct*16, LDB);
                    #pragma unroll
                    for (int p = 0; p < 2; p++){
                        wmma::mma_sync(acc[p][ct], aH[p], bL, acc[p][ct]);
                        wmma::mma_sync(acc[p][ct], aL[p], bH, acc[p][ct]);
                        wmma::mma_sync(acc[p][ct], aH[p], bH, acc[p][ct]);
                    }
                }
            }
            __syncthreads();
        }

        // ---- silu(d + b1), re-split into A tiles ----
        #pragma unroll
        for (int p = 0; p < 2; p++){
            #pragma unroll
            for (int ct = 0; ct < 4; ct++){
                wmma::store_matrix_sync(scr, acc[p][ct], SCRLD, wmma::mem_row_major);
                __syncwarp();
                int c0 = wc + ct*16 + lc;
                float4 v0 = ld4(scr + lr*SCRLD + lc);
                float4 v1 = ld4(scr + lr*SCRLD + lc + 4);
                float4 bb0 = ld4(sB1 + c0);
                float4 bb1 = ld4(sB1 + c0 + 4);
                v0.x = silu_f(v0.x + bb0.x); v0.y = silu_f(v0.y + bb0.y);
                v0.z = silu_f(v0.z + bb0.z); v0.w = silu_f(v0.w + bb0.w);
                v1.x = silu_f(v1.x + bb1.x); v1.y = silu_f(v1.y + bb1.y);
                v1.z = silu_f(v1.z + bb1.z); v1.w = silu_f(v1.w + bb1.w);
                split_store4(sb, OFF_AH, OFF_AL, wr + p*16 + lr, c0,     v0);
                split_store4(sb, OFF_AH, OFF_AL, wr + p*16 + lr, c0 + 4, v1);
                __syncwarp();
            }
        }

        #pragma unroll
        for (int p = 0; p < 2; p++)
            #pragma unroll
            for (int ct = 0; ct < 4; ct++) wmma::fill_fragment(acc[p][ct], 0.f);

        // ================= stage 2: D = H @ W2 (bf16x3) =================
        #pragma unroll
        for (int ks = 0; ks < 8; ks++){
            if (ks < 7){ copy_slice((ks+1)&1, w2 + (ks+1)*WSLICE_BF); cpcommit(); cpwait<1>(); }
            else       { cpwait<0>(); }
            __syncthreads();
            {
                const __nv_bfloat16* bufH = (const __nv_bfloat16*)(sb + OFF_WB + (ks&1)*8704);
                const __nv_bfloat16* bufL = bufH + 2176;
                wmma::fragment<wmma::matrix_a,16,16,16,__nv_bfloat16,wmma::row_major> aH[2], aL[2];
                #pragma unroll
                for (int p = 0; p < 2; p++){
                    wmma::load_matrix_sync(aH[p], pAH + (wr + p*16)*LDB + ks*16, LDB);
                    wmma::load_matrix_sync(aL[p], pAL + (wr + p*16)*LDB + ks*16, LDB);
                }
                #pragma unroll
                for (int ct = 0; ct < 4; ct++){
                    wmma::fragment<wmma::matrix_b,16,16,16,__nv_bfloat16,wmma::row_major> bH, bL;
                    wmma::load_matrix_sync(bH, bufH + wc + ct*16, LDB);
                    wmma::load_matrix_sync(bL, bufL + wc + ct*16, LDB);
                    #pragma unroll
                    for (int p = 0; p < 2; p++){
                        wmma::mma_sync(acc[p][ct], aH[p], bL, acc[p][ct]);
                        wmma::mma_sync(acc[p][ct], aL[p], bH, acc[p][ct]);
                        wmma::mma_sync(acc[p][ct], aH[p], bH, acc[p][ct]);
                    }
                }
            }
            __syncthreads();
        }

        // ================= epilogue =================
        #pragma unroll
        for (int p = 0; p < 2; p++){
            const int row = row0 + wr + p*16 + lr;
            const bool valid = (row < nrows);
            int s = 0, t = 0;
            float d0 = 0.f, d1 = 0.f, d2 = 0.f;
            if (EPI == 4 && valid){
                s = __ldg(eidx + row);
                d0 = __ldg(dispe + (size_t)row*3 + 0);
                d1 = __ldg(dispe + (size_t)row*3 + 1);
                d2 = __ldg(dispe + (size_t)row*3 + 2);
            }
            if (EPI == 2 && valid){
                s = __ldg(eidx + row);
                t = __ldg(eidx + NE + row);
            }
            #pragma unroll
            for (int ct = 0; ct < 4; ct++){
                wmma::store_matrix_sync(scr, acc[p][ct], SCRLD, wmma::mem_row_major);
                __syncwarp();
                if (valid){
                    int c0 = wc + ct*16 + lc;
                    float4 m0 = ld4(scr + lr*SCRLD + lc);
                    float4 m1 = ld4(scr + lr*SCRLD + lc + 4);
                    float4 bb0 = ld4(sB2 + c0);
                    float4 bb1 = ld4(sB2 + c0 + 4);
                    m0.x += bb0.x; m0.y += bb0.y; m0.z += bb0.z; m0.w += bb0.w;
                    m1.x += bb1.x; m1.y += bb1.y; m1.z += bb1.z; m1.w += bb1.w;

                    if (EPI == 0 || EPI == 3){
                        st4(Y + (size_t)row*FD + c0,     m0);
                        st4(Y + (size_t)row*FD + c0 + 4, m1);
                    } else if (EPI == 4){
                        float* bp = accout + (size_t)s*3*FD + c0;
                        red4(bp,            make_float4(m0.x*d0, m0.y*d0, m0.z*d0, m0.w*d0));
                        red4(bp + 4,        make_float4(m1.x*d0, m1.y*d0, m1.z*d0, m1.w*d0));
                        red4(bp + FD,       make_float4(m0.x*d1, m0.y*d1, m0.z*d1, m0.w*d1));
                        red4(bp + FD + 4,   make_float4(m1.x*d1, m1.y*d1, m1.z*d1, m1.w*d1));
                        red4(bp + 2*FD,     make_float4(m0.x*d2, m0.y*d2, m0.z*d2, m0.w*d2));
                        red4(bp + 2*FD + 4, make_float4(m1.x*d2, m1.y*d2, m1.z*d2, m1.w*d2));
                    } else { // EPI == 2: eq2+eq3 fused scatter
                        const float* gp = dispn + (size_t)t*3*FD + c0;
                        const float* pp = empW  + (size_t)t*3*FD + c0;   // empW = P
                        float* bp = accout + (size_t)s*3*FD + c0;
                        #pragma unroll
                        for (int d = 0; d < 3; d++){
                            float4 g0 = ld4(gp + d*FD);
                            float4 g1 = ld4(gp + d*FD + 4);
                            float4 p0 = ld4(pp + d*FD);
                            float4 p1 = ld4(pp + d*FD + 4);
                            red4(bp + d*FD,
                                 make_float4(fmaf(m0.x,g0.x,p0.x), fmaf(m0.y,g0.y,p0.y),
                                             fmaf(m0.z,g0.z,p0.z), fmaf(m0.w,g0.w,p0.w)));
                            red4(bp + d*FD + 4,
                                 make_float4(fmaf(m1.x,g1.x,p1.x), fmaf(m1.y,g1.y,p1.y),
                                             fmaf(m1.z,g1.z,p1.z), fmaf(m1.w,g1.w,p1.w)));
                        }
                    }
                }
                __syncwarp();
            }
        }
        __syncthreads();
    }
}

// ---------------- fused: outF += agg1;  agg1 <- eq3_inv (x) agg1 (P) ----------------
__global__ void forceP_kernel(float* __restrict__ outF){
    int i = blockIdx.x*blockDim.x + threadIdx.x;
    if (i < N3F/4){
        float4 a = ((float4*)g_AGG1)[i];
        float4 f = ((float4*)outF)[i];
        ((float4*)outF)[i] = make_float4(f.x+a.x, f.y+a.y, f.z+a.z, f.w+a.w);
        int node = i / 96;          // 96 float4 per node (3*FD/4)
        int c4   = i % 32;          // column group within FD (96 % 32 == 0)
        float4 g = ((float4*)g_EQ3)[node*32 + c4];
        ((float4*)g_AGG1)[i] = make_float4(a.x*g.x, a.y*g.y, a.z*g.z, a.w*g.w);
    }
}

// ---------------- final: inv_update + layernorm ----------------
__global__ void final_kernel(const float* __restrict__ outF, const float* __restrict__ outD,
                             const float* __restrict__ lng, const float* __restrict__ lnb,
                             float* __restrict__ outA){
    const int i = blockIdx.x;
    const int j = threadIdx.x;   // 128
    float c = 0.f;
    #pragma unroll
    for (int d = 0; d < 3; d++)
        c -= outF[((size_t)i*3 + d)*FD + j] * outD[((size_t)i*3 + d)*FD + j];
    float t = g_ATOM[(size_t)i*FD + j] + g_U[(size_t)i*FD + j] * c;

    __shared__ float red[4];
    float s = t;
    #pragma unroll
    for (int o = 16; o; o >>= 1) s += __shfl_xor_sync(0xffffffffu, s, o);
    if ((j & 31) == 0) red[j >> 5] = s;
    __syncthreads();
    float mu = (red[0]+red[1]+red[2]+red[3]) * (1.f/FD);
    __syncthreads();
    float dv = t - mu;
    float v = dv*dv;
    #pragma unroll
    for (int o = 16; o; o >>= 1) v += __shfl_xor_sync(0xffffffffu, v, o);
    if ((j & 31) == 0) red[j >> 5] = v;
    __syncthreads();
    float var = (red[0]+red[1]+red[2]+red[3]) * (1.f/FD);
    outA[(size_t)i*FD + j] = dv * rsqrtf(var + 1e-5f) * lng[j] + lnb[j];
}

// ---------------- launch ----------------
extern "C" void kernel_launch(void* const* d_in, const int* in_sizes, int n_in,
                              void* d_out, int out_size){
    const float* atom  = (const float*)d_in[0];
    const float* force = (const float*)d_in[1];
    const float* disp  = (const float*)d_in[2];
    const float* dispe = (const float*)d_in[3];
    const float* dist  = (const float*)d_in[4];
    const int*   eidx  = (const int*)  d_in[5];
    const float* nW1 = (const float*)d_in[6],  *nb1 = (const float*)d_in[7];
    const float* nW2 = (const float*)d_in[8],  *nb2 = (const float*)d_in[9];
    const float* eW  = (const float*)d_in[10], *eb  = (const float*)d_in[11];
    const float* q1W1= (const float*)d_in[12], *q1b1= (const float*)d_in[13];
    const float* q1W2= (const float*)d_in[14], *q1b2= (const float*)d_in[15];
    const float* q2W1= (const float*)d_in[16], *q2b1= (const float*)d_in[17];
    const float* q2W2= (const float*)d_in[18], *q2b2= (const float*)d_in[19];
    const float* q3W1= (const float*)d_in[20], *q3W2= (const float*)d_in[21];
    const float* uW1 = (const float*)d_in[22], *ub1 = (const float*)d_in[23];
    const float* uW2 = (const float*)d_in[24], *ub2 = (const float*)d_in[25];
    const float* lng = (const float*)d_in[26], *lnb = (const float*)d_in[27];

    float* out  = (float*)d_out;
    float* outA = out;
    float* outF = out + NF;
    float* outD = out + NF + N3F;

    float *pH, *pAGG, *pATOM, *pEQ3, *pU;
    cudaGetSymbolAddress((void**)&pH,    g_H);
    cudaGetSymbolAddress((void**)&pAGG,  g_AGG1);
    cudaGetSymbolAddress((void**)&pATOM, g_ATOM);
    cudaGetSymbolAddress((void**)&pEQ3,  g_EQ3);
    cudaGetSymbolAddress((void**)&pU,    g_U);
    __nv_bfloat16* pWP;
    cudaGetSymbolAddress((void**)&pWP, g_WP);

    cudaFuncSetAttribute(mlp2_ws<0>, cudaFuncAttributeMaxDynamicSharedMemorySize, SMEM_TOT);
    cudaFuncSetAttribute(mlp2_ws<2>, cudaFuncAttributeMaxDynamicSharedMemorySize, SMEM_TOT);
    cudaFuncSetAttribute(mlp2_ws<3>, cudaFuncAttributeMaxDynamicSharedMemorySize, SMEM_TOT);
    cudaFuncSetAttribute(mlp2_ws<4>, cudaFuncAttributeMaxDynamicSharedMemorySize, SMEM_T4);

    const int NODE_GRID = (NN + TROWS - 1) / TROWS;   // 157
    const int EDGE_GRID = 444;                         // 3 CTAs/SM

    WPtrs P;
    P.w[0]=nW1; P.w[1]=nW2; P.w[2]=q1W1; P.w[3]=q1W2; P.w[4]=q2W1;
    P.w[5]=q2W2; P.w[6]=q3W1; P.w[7]=q3W2; P.w[8]=uW1; P.w[9]=uW2;

    // side stream + fork/join events (created once; host-side resources only)
    static cudaStream_t sB = nullptr;
    static cudaEvent_t evF0, evJ0, evF1, evJ1;
    if (sB == nullptr){
        cudaStreamCreateWithFlags(&sB, cudaStreamNonBlocking);
        cudaEventCreateWithFlags(&evF0, cudaEventDisableTiming);
        cudaEventCreateWithFlags(&evJ0, cudaEventDisableTiming);
        cudaEventCreateWithFlags(&evF1, cudaEventDisableTiming);
        cudaEventCreateWithFlags(&evJ1, cudaEventDisableTiming);
    }

    // ---- fork 0: init (side) || prep_w + h-MLP (main) ----
    cudaEventRecord(evF0, 0);
    cudaStreamWaitEvent(sB, evF0, 0);
    init_kernel<<<N3F/4/256, 256, 0, sB>>>(atom, force, disp, out);

    prep_w<<<80, 256>>>(P);
    mlp2_ws<0><<<NODE_GRID, 128, SMEM_TOT>>>(atom, NN, pWP + 0*WMAT_BF, pWP + 1*WMAT_BF,
                                             nb1, nb2, pH, nullptr, nullptr, nullptr, nullptr,
                                             nullptr, nullptr);
    cudaEventRecord(evJ0, sB);
    cudaStreamWaitEvent(0, evJ0, 0);

    // ---- fused eq1: edge message (split msg -> g_MSGH/L, red4 -> g_ATOM) + eq1 scatter ----
    mlp2_ws<4><<<EDGE_GRID, 128, SMEM_T4>>>(nullptr, NE, pWP + 2*WMAT_BF, pWP + 3*WMAT_BF,
                                            q1b1, q1b2, nullptr, eidx, dispe, dist, pAGG,
                                            eW, eb);

    // ---- fork 1: upd-MLP (side) || eq3inv -> forceP -> fused eq2+eq3 (main) ----
    cudaEventRecord(evF1, 0);
    cudaStreamWaitEvent(sB, evF1, 0);
    mlp2_ws<0><<<NODE_GRID, 128, SMEM_TOT, sB>>>(pATOM, NN, pWP + 8*WMAT_BF, pWP + 9*WMAT_BF,
                                                 ub1, ub2, pU, nullptr, nullptr, nullptr, nullptr,
                                                 nullptr, nullptr);

    mlp2_ws<3><<<NODE_GRID, 128, SMEM_TOT>>>(pATOM, NN, pWP + 6*WMAT_BF, pWP + 7*WMAT_BF,
                                             nullptr, nullptr, pEQ3, nullptr, nullptr, nullptr, nullptr,
                                             nullptr, nullptr);
    forceP_kernel<<<(N3F/4 + 255)/256, 256>>>(outF);
    mlp2_ws<2><<<EDGE_GRID, 128, SMEM_TOT>>>(nullptr, NE, pWP + 4*WMAT_BF, pWP + 5*WMAT_BF,
                                             q2b1, q2b2, nullptr, eidx, nullptr, disp, outD,
                                             pAGG, nullptr);
    cudaEventRecord(evJ1, sB);
    cudaStreamWaitEvent(0, evJ1, 0);

    // ---- join: inv_update coupling + layernorm ----
    final_kernel<<<NN, 128>>>(outF, outD, lng, lnb, outA);
}

// round 17
// speedup vs baseline: 1.1341x; 1.0172x over previous
#include <cuda_runtime.h>
#include <cuda_bf16.h>
#include <math.h>
#include <stdint.h>
#include <mma.h>

using namespace nvcuda;

#define NN 10000
#define NE 200000
#define FD 128
#define NBD 20
#define NF (NN*FD)
#define N3F (NN*3*FD)
#define LDB 136          // bf16 tile leading dim
#define SCRLD 20         // fp32 scratch leading dim
#define TROWS 64         // rows per CTA tile

// byte offsets inside dynamic SMEM (per 128-thread CTA)
#define OFF_AH   0                 // 64 x 136 bf16 = 17408
#define OFF_AL   17408
#define OFF_WB   34816             // 2 weight-slice buffers x 8704 B
#define OFF_SCR  52224             // 4 warps x 16*20*4 = 5120
#define OFF_B1   57344
#define OFF_B2   57856
#define SMEM_TOT 58368
// EPI4 (fused edge-message) extras
#define OFF_EW   58368             // empW 20x128 fp32 = 10240
#define OFF_EB   68608             // empb 512
#define SMEM_T4  69120

#define WSLICE_BF 4352             // bf16 per k-slice block (H 16x136 + L 16x136)
#define WMAT_BF  (8*WSLICE_BF)     // bf16 per prepared matrix

// ---------------- scratch (device globals; no allocation) ----------------
__device__ float g_H[NF];
__device__ __nv_bfloat16 g_MSGH[NE*FD];      // msg hi (bf16)
__device__ __nv_bfloat16 g_MSGL[NE*FD];      // msg lo (bf16)
__device__ float g_AGG1[N3F];                // agg1, then P = eq3inv (x) agg1
__device__ float g_ATOM[NF];
__device__ float g_EQ3[NF];
__device__ float g_U[NF];
__device__ __nv_bfloat16 g_WP[10*WMAT_BF];   // pre-split weights (hi/lo k-slices)

// ---------------- helpers ----------------
__device__ __forceinline__ float4 ld4(const float* p){ return *reinterpret_cast<const float4*>(p); }
__device__ __forceinline__ void st4(float* p, float4 v){ *reinterpret_cast<float4*>(p) = v; }
__device__ __forceinline__ float silu_f(float x){ return x * (1.0f/(1.0f + __expf(-x))); }
__device__ __forceinline__ void red4(float* p, float4 v){
    asm volatile("red.global.add.v4.f32 [%0], {%1,%2,%3,%4};"
        :: "l"(p), "f"(v.x), "f"(v.y), "f"(v.z), "f"(v.w) : "memory");
}
__device__ __forceinline__ uint32_t packbf2(float a, float b){
    __nv_bfloat162 t = __floats2bfloat162_rn(a, b);
    return *reinterpret_cast<uint32_t*>(&t);
}
__device__ __forceinline__ float bf2f(uint32_t u, int half){
    __nv_bfloat162 t = *reinterpret_cast<__nv_bfloat162*>(&u);
    return half ? __bfloat162float(__high2bfloat16(t)) : __bfloat162float(__low2bfloat16(t));
}
__device__ __forceinline__ void cpasync16(uint32_t saddr, const void* gaddr){
    asm volatile("cp.async.cg.shared.global [%0], [%1], 16;" :: "r"(saddr), "l"(gaddr) : "memory");
}
__device__ __forceinline__ void cpcommit(){
    asm volatile("cp.async.commit_group;" ::: "memory");
}
template<int N> __device__ __forceinline__ void cpwait(){
    asm volatile("cp.async.wait_group %0;" :: "n"(N) : "memory");
}

// split x into hi(bf16) + lo(bf16 of residual); write 4 cols to smem tiles;
// optionally also write the packed hi/lo words to global (gh/gl at this row+col).
__device__ __forceinline__ void split_store4(char* sb, int offH, int offL,
                                             int row, int col, float4 v,
                                             __nv_bfloat16* gh = nullptr,
                                             __nv_bfloat16* gl = nullptr){
    uint32_t h0 = packbf2(v.x, v.y);
    uint32_t h1 = packbf2(v.z, v.w);
    float4 r;
    r.x = v.x - bf2f(h0,0); r.y = v.y - bf2f(h0,1);
    r.z = v.z - bf2f(h1,0); r.w = v.w - bf2f(h1,1);
    uint32_t l0 = packbf2(r.x, r.y);
    uint32_t l1 = packbf2(r.z, r.w);
    uint2 hh; hh.x = h0; hh.y = h1;
    uint2 ll; ll.x = l0; ll.y = l1;
    *reinterpret_cast<uint2*>(sb + offH + (row*LDB + col)*2) = hh;
    *reinterpret_cast<uint2*>(sb + offL + (row*LDB + col)*2) = ll;
    if (gh){
        *reinterpret_cast<uint2*>(gh) = hh;
        *reinterpret_cast<uint2*>(gl) = ll;
    }
}

// ---------------- weight prep: fp32 [k][c] -> bf16 hi/lo k-slice blocks ----------------
struct WPtrs { const float* w[10]; };

__global__ void prep_w(WPtrs P){
    int m  = blockIdx.x >> 3;
    int ks = blockIdx.x & 7;
    const float* W = P.w[m];
    __nv_bfloat16* dst = g_WP + m*WMAT_BF + ks*WSLICE_BF;
    for (int e = threadIdx.x; e < 16*FD; e += blockDim.x){
        int kr = e >> 7, c = e & 127;
        float w = W[(ks*16 + kr)*FD + c];
        __nv_bfloat16 h = __float2bfloat16_rn(w);
        __nv_bfloat16 l = __float2bfloat16_rn(w - __bfloat162float(h));
        dst[kr*LDB + c]        = h;
        dst[2176 + kr*LDB + c] = l;
    }
}

// ---------------- init ----------------
__global__ void init_kernel(const float* __restrict__ atom, const float* __restrict__ force,
                            const float* __restrict__ disp, float* __restrict__ out){
    int i = blockIdx.x*blockDim.x + threadIdx.x;
    if (i < N3F/4) {
        ((float4*)(out + NF))[i]        = ((const float4*)force)[i];
        ((float4*)(out + NF + N3F))[i]  = ((const float4*)disp)[i];
        ((float4*)g_AGG1)[i]            = make_float4(0.f,0.f,0.f,0.f);
    }
    if (i < NF/4) ((float4*)g_ATOM)[i] = ((const float4*)atom)[i];
}

// ---------------- bf16x3 wmma fused 2-layer MLP, weight-streaming ----------------
// 128 threads, ONE 64-row tile per CTA, warp block 32x64, 3 CTAs/SM.
// EPI 0: Y with biases   EPI 3: Y no-bias
// EPI 2: eq2+eq3 fused — prologue cp.asyncs pre-split msg (g_MSGH/g_MSGL) into A
//        tiles; epilogue red(accout[src,d,:], m * disp_node[dst,d,:] + P[dst,d,:])
//        where P (=eq3inv (x) agg1, precomputed) arrives via the `empW` slot.
// EPI 4: eq1 with fused edge message: prologue computes
//        e = dist@empW + b; msg = e*h[src]*h[dst]; stores split msg to
//        g_MSGH/g_MSGL, red4s msg into g_ATOM, splits into A tiles.
//        `dispn` carries dist.
template<int EPI>
__global__ void __launch_bounds__(128,3)
mlp2_ws(const float* __restrict__ X, int nrows,
        const __nv_bfloat16* __restrict__ w1, const __nv_bfloat16* __restrict__ w2,
        const float* __restrict__ b1, const float* __restrict__ b2,
        float* __restrict__ Y,
        const int* __restrict__ eidx, const float* __restrict__ dispe,
        const float* __restrict__ dispn, float* __restrict__ accout,
        const float* __restrict__ empW, const float* __restrict__ empb)
{
    extern __shared__ char sb[];
    float* sB1 = (float*)(sb + OFF_B1);
    float* sB2 = (float*)(sb + OFF_B2);

    const int tid  = threadIdx.x;
    const int wid  = tid >> 5;       // 4 warps
    const int lane = tid & 31;

    sB1[tid] = b1 ? b1[tid] : 0.f;
    sB2[tid] = b2 ? b2[tid] : 0.f;

    if (EPI == 4){
        float* sEW = (float*)(sb + OFF_EW);
        float* sEB = (float*)(sb + OFF_EB);
        for (int i = tid; i < NBD*FD; i += 128) sEW[i] = empW[i];
        if (tid < FD) sEB[tid] = empb[tid];
    }
    __syncthreads();

    const __nv_bfloat16* pAH = (const __nv_bfloat16*)(sb + OFF_AH);
    const __nv_bfloat16* pAL = (const __nv_bfloat16*)(sb + OFF_AL);
    float* scr = (float*)(sb + OFF_SCR) + wid*16*SCRLD;
    const uint32_t wb0 = (uint32_t)__cvta_generic_to_shared(sb + OFF_WB);
    const uint32_t uA0 = (uint32_t)__cvta_generic_to_shared(sb);

    const int pr = wid >> 1;            // pair (row group) 0..1
    const int sub = wid & 1;            // column half
    const int wr = pr * 32;
    const int wc = sub * 64;
    const int lr = lane >> 1;           // 0..15
    const int lc = (lane & 1) * 8;      // 0 or 8

    auto copy_slice = [&](int buf, const __nv_bfloat16* src){
        uint32_t dst = wb0 + buf*8704;
        const char* s = (const char*)src;
        #pragma unroll
        for (int j = 0; j < 5; j++){
            int idx = tid + j*128;
            if (idx < 544) cpasync16(dst + idx*16, s + idx*16);
        }
    };

    // ---- ONE tile per CTA (grid sized to tile count; HW scheduler balances) ----
    const int tile = blockIdx.x;
    const int row0 = tile * TROWS;

    if (EPI == 4){
        // ---- compute 16 edge messages per warp (chunked weights in regs) ----
        const float* sEW = (const float*)(sb + OFF_EW);
        const float* sEB = (const float*)(sb + OFF_EB);
        const float4 bias = ld4(sEB + lane*4);
        #pragma unroll
        for (int half = 0; half < 2; half++){
            const int rbase = wid*16 + half*8;
            float4 acc[8];
            #pragma unroll
            for (int r = 0; r < 8; r++) acc[r] = bias;
            #pragma unroll
            for (int cb = 0; cb < 5; cb++){
                float4 w0 = ld4(sEW + (cb*4+0)*FD + lane*4);
                float4 w1v = ld4(sEW + (cb*4+1)*FD + lane*4);
                float4 w2v = ld4(sEW + (cb*4+2)*FD + lane*4);
                float4 w3 = ld4(sEW + (cb*4+3)*FD + lane*4);
                #pragma unroll
                for (int r = 0; r < 8; r++){
                    int e = row0 + rbase + r;
                    if (e < nrows){
                        float4 d = ld4(dispn + (size_t)e*NBD + cb*4);  // dispn = dist
                        acc[r].x = fmaf(d.x, w0.x, acc[r].x);
                        acc[r].y = fmaf(d.x, w0.y, acc[r].y);
                        acc[r].z = fmaf(d.x, w0.z, acc[r].z);
                        acc[r].w = fmaf(d.x, w0.w, acc[r].w);
                        acc[r].x = fmaf(d.y, w1v.x, acc[r].x);
                        acc[r].y = fmaf(d.y, w1v.y, acc[r].y);
                        acc[r].z = fmaf(d.y, w1v.z, acc[r].z);
                        acc[r].w = fmaf(d.y, w1v.w, acc[r].w);
                        acc[r].x = fmaf(d.z, w2v.x, acc[r].x);
                        acc[r].y = fmaf(d.z, w2v.y, acc[r].y);
                        acc[r].z = fmaf(d.z, w2v.z, acc[r].z);
                        acc[r].w = fmaf(d.z, w2v.w, acc[r].w);
                        acc[r].x = fmaf(d.w, w3.x, acc[r].x);
                        acc[r].y = fmaf(d.w, w3.y, acc[r].y);
                        acc[r].z = fmaf(d.w, w3.z, acc[r].z);
                        acc[r].w = fmaf(d.w, w3.w, acc[r].w);
                    }
                }
            }
            #pragma unroll
            for (int r = 0; r < 8; r++){
                int rl = rbase + r;
                int e  = row0 + rl;
                float4 m = make_float4(0.f,0.f,0.f,0.f);
                if (e < nrows){
                    int s = __ldg(eidx + e);
                    int t = __ldg(eidx + NE + e);
                    float4 hs = ld4(g_H + (size_t)s*FD + lane*4);
                    float4 ht = ld4(g_H + (size_t)t*FD + lane*4);
                    m = make_float4(acc[r].x*hs.x*ht.x, acc[r].y*hs.y*ht.y,
                                    acc[r].z*hs.z*ht.z, acc[r].w*hs.w*ht.w);
                    red4(g_ATOM + (size_t)s*FD + lane*4, m);
                    split_store4(sb, OFF_AH, OFF_AL, rl, lane*4, m,
                                 g_MSGH + (size_t)e*FD + lane*4,
                                 g_MSGL + (size_t)e*FD + lane*4);
                } else {
                    split_store4(sb, OFF_AH, OFF_AL, rl, lane*4, m);
                }
            }
        }
    } else if (EPI == 2){
        // ---- cp.async pre-split msg rows straight into A tiles ----
        const int chunk = lane & 15;            // 16B chunk within row
        const int hl    = lane >> 4;            // 0 = hi, 1 = lo
        const __nv_bfloat16* gsrc = hl ? g_MSGL : g_MSGH;
        const uint32_t dbase = uA0 + (hl ? OFF_AL : OFF_AH);
        #pragma unroll 4
        for (int rr = 0; rr < 16; rr++){
            int rl  = wid*16 + rr;
            int row = row0 + rl;                 // NE % 64 == 0: always valid
            cpasync16(dbase + (uint32_t)rl*272 + chunk*16,
                      (const char*)(gsrc + (size_t)row*FD) + chunk*16);
        }
        cpcommit();
    } else {
        #pragma unroll 4
        for (int rr = 0; rr < 16; rr++){
            int rl  = wid*16 + rr;
            int row = row0 + rl;
            float4 v = make_float4(0.f,0.f,0.f,0.f);
            if (row < nrows) v = ld4(X + (size_t)row*FD + lane*4);
            split_store4(sb, OFF_AH, OFF_AL, rl, lane*4, v);
        }
    }

    copy_slice(0, w1); cpcommit();

    wmma::fragment<wmma::accumulator,16,16,16,float> acc[2][4];
    #pragma unroll
    for (int p = 0; p < 2; p++)
        #pragma unroll
        for (int ct = 0; ct < 4; ct++) wmma::fill_fragment(acc[p][ct], 0.f);

    // ================= stage 1: D = X @ W1 (bf16x3) =================
    #pragma unroll
    for (int ks = 0; ks < 8; ks++){
        if (ks < 7) copy_slice((ks+1)&1, w1 + (ks+1)*WSLICE_BF);
        else        copy_slice(0,        w2);
        cpcommit();
        cpwait<1>();
        __syncthreads();
        {
            const __nv_bfloat16* bufH = (const __nv_bfloat16*)(sb + OFF_WB + (ks&1)*8704);
            const __nv_bfloat16* bufL = bufH + 2176;
            wmma::fragment<wmma::matrix_a,16,16,16,__nv_bfloat16,wmma::row_major> aH[2], aL[2];
            #pragma unroll
            for (int p = 0; p < 2; p++){
                wmma::load_matrix_sync(aH[p], pAH + (wr + p*16)*LDB + ks*16, LDB);
                wmma::load_matrix_sync(aL[p], pAL + (wr + p*16)*LDB + ks*16, LDB);
            }
            #pragma unroll
            for (int ct = 0; ct < 4; ct++){
                wmma::fragment<wmma::matrix_b,16,16,16,__nv_bfloat16,wmma::row_major> bH, bL;
                wmma::load_matrix_sync(bH, bufH + wc + ct*16, LDB);
                wmma::load_matrix_sync(bL, bufL + wc + ct*16, LDB);
                #pragma unroll
                for (int p = 0; p < 2; p++){
                    wmma::mma_sync(acc[p][ct], aH[p], bL, acc[p][ct]);
                    wmma::mma_sync(acc[p][ct], aL[p], bH, acc[p][ct]);
                    wmma::mma_sync(acc[p][ct], aH[p], bH, acc[p][ct]);
                }
            }
        }
        __syncthreads();
    }

    // ---- silu(d + b1), re-split into A tiles ----
    #pragma unroll
    for (int p = 0; p < 2; p++){
        #pragma unroll
        for (int ct = 0; ct < 4; ct++){
            wmma::store_matrix_sync(scr, acc[p][ct], SCRLD, wmma::mem_row_major);
            __syncwarp();
            int c0 = wc + ct*16 + lc;
            float4 v0 = ld4(scr + lr*SCRLD + lc);
            float4 v1 = ld4(scr + lr*SCRLD + lc + 4);
            float4 bb0 = ld4(sB1 + c0);
            float4 bb1 = ld4(sB1 + c0 + 4);
            v0.x = silu_f(v0.x + bb0.x); v0.y = silu_f(v0.y + bb0.y);
            v0.z = silu_f(v0.z + bb0.z); v0.w = silu_f(v0.w + bb0.w);
            v1.x = silu_f(v1.x + bb1.x); v1.y = silu_f(v1.y + bb1.y);
            v1.z = silu_f(v1.z + bb1.z); v1.w = silu_f(v1.w + bb1.w);
            split_store4(sb, OFF_AH, OFF_AL, wr + p*16 + lr, c0,     v0);
            split_store4(sb, OFF_AH, OFF_AL, wr + p*16 + lr, c0 + 4, v1);
            __syncwarp();
        }
    }

    #pragma unroll
    for (int p = 0; p < 2; p++)
        #pragma unroll
        for (int ct = 0; ct < 4; ct++) wmma::fill_fragment(acc[p][ct], 0.f);

    // ================= stage 2: D = H @ W2 (bf16x3) =================
    #pragma unroll
    for (int ks = 0; ks < 8; ks++){
        if (ks < 7){ copy_slice((ks+1)&1, w2 + (ks+1)*WSLICE_BF); cpcommit(); cpwait<1>(); }
        else       { cpwait<0>(); }
        __syncthreads();
        {
            const __nv_bfloat16* bufH = (const __nv_bfloat16*)(sb + OFF_WB + (ks&1)*8704);
            const __nv_bfloat16* bufL = bufH + 2176;
            wmma::fragment<wmma::matrix_a,16,16,16,__nv_bfloat16,wmma::row_major> aH[2], aL[2];
            #pragma unroll
            for (int p = 0; p < 2; p++){
                wmma::load_matrix_sync(aH[p], pAH + (wr + p*16)*LDB + ks*16, LDB);
                wmma::load_matrix_sync(aL[p], pAL + (wr + p*16)*LDB + ks*16, LDB);
            }
            #pragma unroll
            for (int ct = 0; ct < 4; ct++){
                wmma::fragment<wmma::matrix_b,16,16,16,__nv_bfloat16,wmma::row_major> bH, bL;
                wmma::load_matrix_sync(bH, bufH + wc + ct*16, LDB);
                wmma::load_matrix_sync(bL, bufL + wc + ct*16, LDB);
                #pragma unroll
                for (int p = 0; p < 2; p++){
                    wmma::mma_sync(acc[p][ct], aH[p], bL, acc[p][ct]);
                    wmma::mma_sync(acc[p][ct], aL[p], bH, acc[p][ct]);
                    wmma::mma_sync(acc[p][ct], aH[p], bH, acc[p][ct]);
                }
            }
        }
        __syncthreads();
    }

    // ================= epilogue =================
    #pragma unroll
    for (int p = 0; p < 2; p++){
        const int row = row0 + wr + p*16 + lr;
        const bool valid = (row < nrows);
        int s = 0, t = 0;
        float d0 = 0.f, d1 = 0.f, d2 = 0.f;
        if (EPI == 4 && valid){
            s = __ldg(eidx + row);
            d0 = __ldg(dispe + (size_t)row*3 + 0);
            d1 = __ldg(dispe + (size_t)row*3 + 1);
            d2 = __ldg(dispe + (size_t)row*3 + 2);
        }
        if (EPI == 2 && valid){
            s = __ldg(eidx + row);
            t = __ldg(eidx + NE + row);
        }
        #pragma unroll
        for (int ct = 0; ct < 4; ct++){
            wmma::store_matrix_sync(scr, acc[p][ct], SCRLD, wmma::mem_row_major);
            __syncwarp();
            if (valid){
                int c0 = wc + ct*16 + lc;
                float4 m0 = ld4(scr + lr*SCRLD + lc);
                float4 m1 = ld4(scr + lr*SCRLD + lc + 4);
                float4 bb0 = ld4(sB2 + c0);
                float4 bb1 = ld4(sB2 + c0 + 4);
                m0.x += bb0.x; m0.y += bb0.y; m0.z += bb0.z; m0.w += bb0.w;
                m1.x += bb1.x; m1.y += bb1.y; m1.z += bb1.z; m1.w += bb1.w;

                if (EPI == 0 || EPI == 3){
                    st4(Y + (size_t)row*FD + c0,     m0);
                    st4(Y + (size_t)row*FD + c0 + 4, m1);
                } else if (EPI == 4){
                    float* bp = accout + (size_t)s*3*FD + c0;
                    red4(bp,            make_float4(m0.x*d0, m0.y*d0, m0.z*d0, m0.w*d0));
                    red4(bp + 4,        make_float4(m1.x*d0, m1.y*d0, m1.z*d0, m1.w*d0));
                    red4(bp + FD,       make_float4(m0.x*d1, m0.y*d1, m0.z*d1, m0.w*d1));
                    red4(bp + FD + 4,   make_float4(m1.x*d1, m1.y*d1, m1.z*d1, m1.w*d1));
                    red4(bp + 2*FD,     make_float4(m0.x*d2, m0.y*d2, m0.z*d2, m0.w*d2));
                    red4(bp + 2*FD + 4, make_float4(m1.x*d2, m1.y*d2, m1.z*d2, m1.w*d2));
                } else { // EPI == 2: eq2+eq3 fused scatter
                    const float* gp = dispn + (size_t)t*3*FD + c0;
                    const float* pp = empW  + (size_t)t*3*FD + c0;   // empW = P
                    float* bp = accout + (size_t)s*3*FD + c0;
                    #pragma unroll
                    for (int d = 0; d < 3; d++){
                        float4 g0 = ld4(gp + d*FD);
                        float4 g1 = ld4(gp + d*FD + 4);
                        float4 p0 = ld4(pp + d*FD);
                        float4 p1 = ld4(pp + d*FD + 4);
                        red4(bp + d*FD,
                             make_float4(fmaf(m0.x,g0.x,p0.x), fmaf(m0.y,g0.y,p0.y),
                                         fmaf(m0.z,g0.z,p0.z), fmaf(m0.w,g0.w,p0.w)));
                        red4(bp + d*FD + 4,
                             make_float4(fmaf(m1.x,g1.x,p1.x), fmaf(m1.y,g1.y,p1.y),
                                         fmaf(m1.z,g1.z,p1.z), fmaf(m1.w,g1.w,p1.w)));
                    }
                }
            }
            __syncwarp();
        }
    }
}

// ---------------- fused: outF += agg1;  agg1 <- eq3_inv (x) agg1 (P) ----------------
__global__ void forceP_kernel(float* __restrict__ outF){
    int i = blockIdx.x*blockDim.x + threadIdx.x;
    if (i < N3F/4){
        float4 a = ((float4*)g_AGG1)[i];
        float4 f = ((float4*)outF)[i];
        ((float4*)outF)[i] = make_float4(f.x+a.x, f.y+a.y, f.z+a.z, f.w+a.w);
        int node = i / 96;          // 96 float4 per node (3*FD/4)
        int c4   = i % 32;          // column group within FD (96 % 32 == 0)
        float4 g = ((float4*)g_EQ3)[node*32 + c4];
        ((float4*)g_AGG1)[i] = make_float4(a.x*g.x, a.y*g.y, a.z*g.z, a.w*g.w);
    }
}

// ---------------- final: inv_update + layernorm ----------------
__global__ void final_kernel(const float* __restrict__ outF, const float* __restrict__ outD,
                             const float* __restrict__ lng, const float* __restrict__ lnb,
                             float* __restrict__ outA){
    const int i = blockIdx.x;
    const int j = threadIdx.x;   // 128
    float c = 0.f;
    #pragma unroll
    for (int d = 0; d < 3; d++)
        c -= outF[((size_t)i*3 + d)*FD + j] * outD[((size_t)i*3 + d)*FD + j];
    float t = g_ATOM[(size_t)i*FD + j] + g_U[(size_t)i*FD + j] * c;

    __shared__ float red[4];
    float s = t;
    #pragma unroll
    for (int o = 16; o; o >>= 1) s += __shfl_xor_sync(0xffffffffu, s, o);
    if ((j & 31) == 0) red[j >> 5] = s;
    __syncthreads();
    float mu = (red[0]+red[1]+red[2]+red[3]) * (1.f/FD);
    __syncthreads();
    float dv = t - mu;
    float v = dv*dv;
    #pragma unroll
    for (int o = 16; o; o >>= 1) v += __shfl_xor_sync(0xffffffffu, v, o);
    if ((j & 31) == 0) red[j >> 5] = v;
    __syncthreads();
    float var = (red[0]+red[1]+red[2]+red[3]) * (1.f/FD);
    outA[(size_t)i*FD + j] = dv * rsqrtf(var + 1e-5f) * lng[j] + lnb[j];
}

// ---------------- launch ----------------
extern "C" void kernel_launch(void* const* d_in, const int* in_sizes, int n_in,
                              void* d_out, int out_size){
    const float* atom  = (const float*)d_in[0];
    const float* force = (const float*)d_in[1];
    const float* disp  = (const float*)d_in[2];
    const float* dispe = (const float*)d_in[3];
    const float* dist  = (const float*)d_in[4];
    const int*   eidx  = (const int*)  d_in[5];
    const float* nW1 = (const float*)d_in[6],  *nb1 = (const float*)d_in[7];
    const float* nW2 = (const float*)d_in[8],  *nb2 = (const float*)d_in[9];
    const float* eW  = (const float*)d_in[10], *eb  = (const float*)d_in[11];
    const float* q1W1= (const float*)d_in[12], *q1b1= (const float*)d_in[13];
    const float* q1W2= (const float*)d_in[14], *q1b2= (const float*)d_in[15];
    const float* q2W1= (const float*)d_in[16], *q2b1= (const float*)d_in[17];
    const float* q2W2= (const float*)d_in[18], *q2b2= (const float*)d_in[19];
    const float* q3W1= (const float*)d_in[20], *q3W2= (const float*)d_in[21];
    const float* uW1 = (const float*)d_in[22], *ub1 = (const float*)d_in[23];
    const float* uW2 = (const float*)d_in[24], *ub2 = (const float*)d_in[25];
    const float* lng = (const float*)d_in[26], *lnb = (const float*)d_in[27];

    float* out  = (float*)d_out;
    float* outA = out;
    float* outF = out + NF;
    float* outD = out + NF + N3F;

    float *pH, *pAGG, *pATOM, *pEQ3, *pU;
    cudaGetSymbolAddress((void**)&pH,    g_H);
    cudaGetSymbolAddress((void**)&pAGG,  g_AGG1);
    cudaGetSymbolAddress((void**)&pATOM, g_ATOM);
    cudaGetSymbolAddress((void**)&pEQ3,  g_EQ3);
    cudaGetSymbolAddress((void**)&pU,    g_U);
    __nv_bfloat16* pWP;
    cudaGetSymbolAddress((void**)&pWP, g_WP);

    cudaFuncSetAttribute(mlp2_ws<0>, cudaFuncAttributeMaxDynamicSharedMemorySize, SMEM_TOT);
    cudaFuncSetAttribute(mlp2_ws<2>, cudaFuncAttributeMaxDynamicSharedMemorySize, SMEM_TOT);
    cudaFuncSetAttribute(mlp2_ws<3>, cudaFuncAttributeMaxDynamicSharedMemorySize, SMEM_TOT);
    cudaFuncSetAttribute(mlp2_ws<4>, cudaFuncAttributeMaxDynamicSharedMemorySize, SMEM_T4);

    const int NODE_GRID = (NN + TROWS - 1) / TROWS;   // 157 (1 tile per CTA)
    const int EDGE_GRID = NE / TROWS;                  // 3125 (1 tile per CTA)

    WPtrs P;
    P.w[0]=nW1; P.w[1]=nW2; P.w[2]=q1W1; P.w[3]=q1W2; P.w[4]=q2W1;
    P.w[5]=q2W2; P.w[6]=q3W1; P.w[7]=q3W2; P.w[8]=uW1; P.w[9]=uW2;

    // side stream + fork/join events (created once; host-side resources only)
    static cudaStream_t sB = nullptr;
    static cudaEvent_t evF0, evJ0, evF1, evJ1;
    if (sB == nullptr){
        cudaStreamCreateWithFlags(&sB, cudaStreamNonBlocking);
        cudaEventCreateWithFlags(&evF0, cudaEventDisableTiming);
        cudaEventCreateWithFlags(&evJ0, cudaEventDisableTiming);
        cudaEventCreateWithFlags(&evF1, cudaEventDisableTiming);
        cudaEventCreateWithFlags(&evJ1, cudaEventDisableTiming);
    }

    // ---- fork 0: init (side) || prep_w + h-MLP (main) ----
    cudaEventRecord(evF0, 0);
    cudaStreamWaitEvent(sB, evF0, 0);
    init_kernel<<<N3F/4/256, 256, 0, sB>>>(atom, force, disp, out);

    prep_w<<<80, 256>>>(P);
    mlp2_ws<0><<<NODE_GRID, 128, SMEM_TOT>>>(atom, NN, pWP + 0*WMAT_BF, pWP + 1*WMAT_BF,
                                             nb1, nb2, pH, nullptr, nullptr, nullptr, nullptr,
                                             nullptr, nullptr);
    cudaEventRecord(evJ0, sB);
    cudaStreamWaitEvent(0, evJ0, 0);

    // ---- fused eq1: edge message (split msg -> g_MSGH/L, red4 -> g_ATOM) + eq1 scatter ----
    mlp2_ws<4><<<EDGE_GRID, 128, SMEM_T4>>>(nullptr, NE, pWP + 2*WMAT_BF, pWP + 3*WMAT_BF,
                                            q1b1, q1b2, nullptr, eidx, dispe, dist, pAGG,
                                            eW, eb);

    // ---- fork 1: upd-MLP (side) || eq3inv -> forceP -> fused eq2+eq3 (main) ----
    cudaEventRecord(evF1, 0);
    cudaStreamWaitEvent(sB, evF1, 0);
    mlp2_ws<0><<<NODE_GRID, 128, SMEM_TOT, sB>>>(pATOM, NN, pWP + 8*WMAT_BF, pWP + 9*WMAT_BF,
                                                 ub1, ub2, pU, nullptr, nullptr, nullptr, nullptr,
                                                 nullptr, nullptr);

    mlp2_ws<3><<<NODE_GRID, 128, SMEM_TOT>>>(pATOM, NN, pWP + 6*WMAT_BF, pWP + 7*WMAT_BF,
                                             nullptr, nullptr, pEQ3, nullptr, nullptr, nullptr, nullptr,
                                             nullptr, nullptr);
    forceP_kernel<<<(N3F/4 + 255)/256, 256>>>(outF);
    mlp2_ws<2><<<EDGE_GRID, 128, SMEM_TOT>>>(nullptr, NE, pWP + 4*WMAT_BF, pWP + 5*WMAT_BF,
                                             q2b1, q2b2, nullptr, eidx, nullptr, disp, outD,
                                             pAGG, nullptr);
    cudaEventRecord(evJ1, sB);
    cudaStreamWaitEvent(0, evJ1, 0);

    // ---- join: inv_update coupling + layernorm ----
    final_kernel<<<NN, 128>>>(outF, outD, lng, lnb, outA);
}